// round 1
// baseline (speedup 1.0000x reference)
#include <cuda_runtime.h>
#include <math.h>

#define HH 16
#define NN 4096
#define DD 64
#define MM 256
#define ROWS (HH * NN)          // 65536

#define NORMALIZER 0.35355339059327373f  // 64^-0.25
#define DIAG_COEF  0.0625f               // 0.5 * 64^-0.5
#define RATIO      0.0625f               // 256^-0.5
#define FEPS       1e-4f

// ---------------- scratch (device globals; no allocation allowed) -------------
__device__ float g_qp[(size_t)ROWS * MM];   // q dash -> q features (in place)
__device__ float g_kp[(size_t)ROWS * MM];   // k dash -> k features (in place)
__device__ float g_qdiag[ROWS];
__device__ float g_kdiag[ROWS];
__device__ float g_ksum[HH * MM];
__device__ float g_dinv[ROWS];
__device__ float g_ctx[HH * MM * DD];
__device__ float g_kpart[1024];
__device__ float g_kmax[1];

// ---------------- zero accumulated scratch (every launch) ---------------------
__global__ void zero_kernel() {
    int i = blockIdx.x * 256 + threadIdx.x;          // grid = HH*MM*DD/256 = 1024
    if (i < HH * MM) g_ksum[i] = 0.f;
    g_ctx[i] = 0.f;
}

// ---------------- generic NT SGEMM: C[I,J] = alpha * A[I,K] * B[J,K]^T --------
// 128x128 tile, BK=16, 256 threads, 8x8 microtile (4+4 split for coalesced C).
__global__ __launch_bounds__(256) void nt_gemm128(
    const float* __restrict__ A, const float* __restrict__ B, float* __restrict__ C,
    int K, int ldc, long sA, long sB, long sC, float alpha)
{
    A += (long)blockIdx.z * sA;
    B += (long)blockIdx.z * sB;
    C += (long)blockIdx.z * sC;
    const int i0 = blockIdx.x * 128;
    const int j0 = blockIdx.y * 128;

    __shared__ float As[16][132];
    __shared__ float Bs[16][132];

    const int t  = threadIdx.x;
    const int tx = t & 15;
    const int ty = t >> 4;

    float acc[8][8];
#pragma unroll
    for (int i = 0; i < 8; ++i)
#pragma unroll
        for (int j = 0; j < 8; ++j) acc[i][j] = 0.f;

    for (int k0 = 0; k0 < K; k0 += 16) {
#pragma unroll
        for (int l = 0; l < 2; ++l) {
            int idx = t + l * 256;
            int row = idx >> 2;
            int kq  = (idx & 3) << 2;
            float4 va = *(const float4*)(A + (long)(i0 + row) * K + k0 + kq);
            As[kq + 0][row] = va.x; As[kq + 1][row] = va.y;
            As[kq + 2][row] = va.z; As[kq + 3][row] = va.w;
            float4 vb = *(const float4*)(B + (long)(j0 + row) * K + k0 + kq);
            Bs[kq + 0][row] = vb.x; Bs[kq + 1][row] = vb.y;
            Bs[kq + 2][row] = vb.z; Bs[kq + 3][row] = vb.w;
        }
        __syncthreads();
#pragma unroll
        for (int k = 0; k < 16; ++k) {
            float4 a0 = *(const float4*)&As[k][ty * 4];
            float4 a1 = *(const float4*)&As[k][64 + ty * 4];
            float4 b0 = *(const float4*)&Bs[k][tx * 4];
            float4 b1 = *(const float4*)&Bs[k][64 + tx * 4];
            float a[8] = {a0.x, a0.y, a0.z, a0.w, a1.x, a1.y, a1.z, a1.w};
            float b[8] = {b0.x, b0.y, b0.z, b0.w, b1.x, b1.y, b1.z, b1.w};
#pragma unroll
            for (int i = 0; i < 8; ++i)
#pragma unroll
                for (int j = 0; j < 8; ++j)
                    acc[i][j] += a[i] * b[j];
        }
        __syncthreads();
    }

#pragma unroll
    for (int i = 0; i < 8; ++i) {
        int r = i0 + ((i < 4) ? (ty * 4 + i) : (64 + ty * 4 + i - 4));
        float* cp = C + (long)r * ldc + j0;
        float4 v0 = make_float4(acc[i][0] * alpha, acc[i][1] * alpha,
                                acc[i][2] * alpha, acc[i][3] * alpha);
        float4 v1 = make_float4(acc[i][4] * alpha, acc[i][5] * alpha,
                                acc[i][6] * alpha, acc[i][7] * alpha);
        *(float4*)(cp + tx * 4)      = v0;
        *(float4*)(cp + 64 + tx * 4) = v1;
    }
}

// ---------------- diag[row] = DIAG_COEF * sum_d x[row][d]^2 -------------------
__global__ void diag_kernel(const float* __restrict__ x, float* __restrict__ out) {
    int row  = blockIdx.x * 8 + (threadIdx.x >> 5);
    int lane = threadIdx.x & 31;
    const float* p = x + (long)row * DD;
    float a = p[lane], b = p[lane + 32];
    float s = a * a + b * b;
#pragma unroll
    for (int o = 16; o; o >>= 1) s += __shfl_xor_sync(0xffffffffu, s, o);
    if (!lane) out[row] = s * DIAG_COEF;
}

// ---------------- global max over k dash (2-stage) -----------------------------
__global__ void kmax1_kernel(const float* __restrict__ d, float* __restrict__ part, int n) {
    float m = -3.4e38f;
    for (int i = blockIdx.x * blockDim.x + threadIdx.x; i < n; i += gridDim.x * blockDim.x)
        m = fmaxf(m, d[i]);
    __shared__ float sm[8];
#pragma unroll
    for (int o = 16; o; o >>= 1) m = fmaxf(m, __shfl_xor_sync(0xffffffffu, m, o));
    if ((threadIdx.x & 31) == 0) sm[threadIdx.x >> 5] = m;
    __syncthreads();
    if (threadIdx.x == 0) {
        float b = sm[0];
#pragma unroll
        for (int w = 1; w < 8; ++w) b = fmaxf(b, sm[w]);
        part[blockIdx.x] = b;
    }
}

__global__ void kmax2_kernel(const float* __restrict__ part, float* __restrict__ out, int n) {
    float m = -3.4e38f;
    for (int i = threadIdx.x; i < n; i += 256) m = fmaxf(m, part[i]);
    __shared__ float sm[8];
#pragma unroll
    for (int o = 16; o; o >>= 1) m = fmaxf(m, __shfl_xor_sync(0xffffffffu, m, o));
    if ((threadIdx.x & 31) == 0) sm[threadIdx.x >> 5] = m;
    __syncthreads();
    if (threadIdx.x == 0) {
        float b = sm[0];
#pragma unroll
        for (int w = 1; w < 8; ++w) b = fmaxf(b, sm[w]);
        out[0] = b;
    }
}

// ---------------- q features: per-row max stabilizer, exp, in place ------------
__global__ void expq_kernel(float* __restrict__ dash, const float* __restrict__ diag) {
    long row = blockIdx.x;
    int  t   = threadIdx.x;
    long idx = row * MM + t;
    float x = dash[idx];
    float m = x;
#pragma unroll
    for (int o = 16; o; o >>= 1) m = fmaxf(m, __shfl_xor_sync(0xffffffffu, m, o));
    __shared__ float sm[8];
    if ((t & 31) == 0) sm[t >> 5] = m;
    __syncthreads();
    float bm = sm[0];
#pragma unroll
    for (int w = 1; w < 8; ++w) bm = fmaxf(bm, sm[w]);
    dash[idx] = RATIO * (expf(x - diag[row] - bm) + FEPS);
}

// ---------------- k features: global stabilizer, exp, fused column sums --------
__global__ void expk_kernel(float* __restrict__ dash, const float* __restrict__ diag,
                            const float* __restrict__ kmax, float* __restrict__ ksum) {
    int t    = threadIdx.x;
    int row0 = blockIdx.x * 64;
    int h    = row0 >> 12;
    float stab  = kmax[0];
    float local = 0.f;
    for (int r = 0; r < 64; ++r) {
        long idx = (long)(row0 + r) * MM + t;
        float vv = RATIO * (expf(dash[idx] - diag[row0 + r] - stab) + FEPS);
        dash[idx] = vv;
        local += vv;
    }
    atomicAdd(&ksum[h * MM + t], local);
}

// ---------------- context[h][m][e] = sum_n kp[h][n][m] * v[h][n][e] -----------
// grid (mtile=4, kchunk=8, h=16), split-K with atomics into g_ctx.
__global__ __launch_bounds__(256) void ctx_kernel(const float* __restrict__ kp,
                                                  const float* __restrict__ v,
                                                  float* __restrict__ ctx) {
    int h  = blockIdx.z;
    int m0 = blockIdx.x * 64;
    int n0 = blockIdx.y * 512;
    __shared__ float kps[16][64];
    __shared__ float vs[16][64];
    int t  = threadIdx.x;
    int ti = t >> 4, tj = t & 15;
    int lr = t >> 4, lf = t & 15;
    float acc[4][4];
#pragma unroll
    for (int i = 0; i < 4; ++i)
#pragma unroll
        for (int j = 0; j < 4; ++j) acc[i][j] = 0.f;

    const float* kpb = kp + (long)h * NN * MM;
    const float* vb  = v  + (long)h * NN * DD;

    for (int nb = 0; nb < 32; ++nb) {
        int n = n0 + nb * 16 + lr;
        *(float4*)&kps[lr][lf * 4] = *(const float4*)(kpb + (long)n * MM + m0 + lf * 4);
        *(float4*)&vs[lr][lf * 4]  = *(const float4*)(vb  + (long)n * DD + lf * 4);
        __syncthreads();
#pragma unroll
        for (int nn = 0; nn < 16; ++nn) {
            float4 a4 = *(const float4*)&kps[nn][ti * 4];
            float4 b4 = *(const float4*)&vs[nn][tj * 4];
            float a[4] = {a4.x, a4.y, a4.z, a4.w};
            float b[4] = {b4.x, b4.y, b4.z, b4.w};
#pragma unroll
            for (int i = 0; i < 4; ++i)
#pragma unroll
                for (int j = 0; j < 4; ++j) acc[i][j] += a[i] * b[j];
        }
        __syncthreads();
    }
#pragma unroll
    for (int i = 0; i < 4; ++i)
#pragma unroll
        for (int j = 0; j < 4; ++j)
            atomicAdd(&ctx[((long)h * MM + m0 + ti * 4 + i) * DD + tj * 4 + j], acc[i][j]);
}

// ---------------- d_inv[row] = 1 / dot(qp[row], ksum[h]) ----------------------
__global__ void dinv_kernel(const float* __restrict__ qp, const float* __restrict__ ksum,
                            float* __restrict__ dinv) {
    int row  = blockIdx.x * 8 + (threadIdx.x >> 5);
    int lane = threadIdx.x & 31;
    int h    = row >> 12;
    const float* qr = qp + (long)row * MM;
    const float* ks = ksum + h * MM;
    float s = 0.f;
#pragma unroll
    for (int i = 0; i < 8; ++i) {
        int m = lane + i * 32;
        s += qr[m] * ks[m];
    }
#pragma unroll
    for (int o = 16; o; o >>= 1) s += __shfl_xor_sync(0xffffffffu, s, o);
    if (!lane) dinv[row] = 1.f / s;
}

// ---------------- out[h][n][e] = dinv * sum_m qp[h][n][m] * ctx[h][m][e] ------
__global__ __launch_bounds__(256) void out_kernel(const float* __restrict__ qp,
                                                  const float* __restrict__ ctx,
                                                  const float* __restrict__ dinv,
                                                  float* __restrict__ out) {
    int h  = blockIdx.y;
    int n0 = blockIdx.x * 64;
    __shared__ float qps[64][17];
    __shared__ float cs[16][64];
    int t  = threadIdx.x;
    int ti = t >> 4, tj = t & 15;
    float acc[4][4];
#pragma unroll
    for (int i = 0; i < 4; ++i)
#pragma unroll
        for (int j = 0; j < 4; ++j) acc[i][j] = 0.f;

    const float* qpb = qp + ((long)h * NN + n0) * MM;
    const float* cb  = ctx + (long)h * MM * DD;

    for (int mb = 0; mb < 16; ++mb) {
        {   // qp tile: 64 rows x 16 m
            int r  = t >> 2;
            int cq = (t & 3) * 4;
            float4 vq = *(const float4*)(qpb + (long)r * MM + mb * 16 + cq);
            qps[r][cq + 0] = vq.x; qps[r][cq + 1] = vq.y;
            qps[r][cq + 2] = vq.z; qps[r][cq + 3] = vq.w;
        }
        {   // ctx tile: 16 m x 64 e
            int mr = t >> 4, f = t & 15;
            *(float4*)&cs[mr][f * 4] = *(const float4*)(cb + (long)(mb * 16 + mr) * DD + f * 4);
        }
        __syncthreads();
#pragma unroll
        for (int k = 0; k < 16; ++k) {
            float a[4];
#pragma unroll
            for (int i = 0; i < 4; ++i) a[i] = qps[ti * 4 + i][k];
            float4 b4 = *(const float4*)&cs[k][tj * 4];
            float b[4] = {b4.x, b4.y, b4.z, b4.w};
#pragma unroll
            for (int i = 0; i < 4; ++i)
#pragma unroll
                for (int j = 0; j < 4; ++j) acc[i][j] += a[i] * b[j];
        }
        __syncthreads();
    }
#pragma unroll
    for (int i = 0; i < 4; ++i) {
        int n = n0 + ti * 4 + i;
        float dv = dinv[(long)h * NN + n];
        float4 o = make_float4(acc[i][0] * dv, acc[i][1] * dv, acc[i][2] * dv, acc[i][3] * dv);
        *(float4*)(out + ((long)h * NN + n) * DD + tj * 4) = o;
    }
}

// -------------------------------------------------------------------------------
extern "C" void kernel_launch(void* const* d_in, const int* in_sizes, int n_in,
                              void* d_out, int out_size)
{
    const float* q    = (const float*)d_in[0];
    const float* k    = (const float*)d_in[1];
    const float* v    = (const float*)d_in[2];
    const float* proj = (const float*)d_in[3];

    float* out_align = (float*)d_out;                       // [H,N,D]
    float* out_w     = out_align + (long)HH * NN * DD;      // [H,N,N]

    float *qp, *kp, *qdiag, *kdiag, *ksum, *dinv, *ctx, *kpart, *kmax;
    cudaGetSymbolAddress((void**)&qp,    g_qp);
    cudaGetSymbolAddress((void**)&kp,    g_kp);
    cudaGetSymbolAddress((void**)&qdiag, g_qdiag);
    cudaGetSymbolAddress((void**)&kdiag, g_kdiag);
    cudaGetSymbolAddress((void**)&ksum,  g_ksum);
    cudaGetSymbolAddress((void**)&dinv,  g_dinv);
    cudaGetSymbolAddress((void**)&ctx,   g_ctx);
    cudaGetSymbolAddress((void**)&kpart, g_kpart);
    cudaGetSymbolAddress((void**)&kmax,  g_kmax);

    zero_kernel<<<HH * MM * DD / 256, 256>>>();

    // dash = normalizer * (data @ proj^T)
    nt_gemm128<<<dim3(ROWS / 128, MM / 128, 1), 256>>>(q, proj, qp, DD, MM, 0, 0, 0, NORMALIZER);
    nt_gemm128<<<dim3(ROWS / 128, MM / 128, 1), 256>>>(k, proj, kp, DD, MM, 0, 0, 0, NORMALIZER);

    diag_kernel<<<ROWS / 8, 256>>>(q, qdiag);
    diag_kernel<<<ROWS / 8, 256>>>(k, kdiag);

    kmax1_kernel<<<1024, 256>>>(kp, kpart, ROWS * MM);
    kmax2_kernel<<<1, 256>>>(kpart, kmax, 1024);

    expq_kernel<<<ROWS, 256>>>(qp, qdiag);
    expk_kernel<<<ROWS / 64, 256>>>(kp, kdiag, kmax, ksum);

    // weights[h] = qp[h] @ kp[h]^T   (dominant GEMM)
    nt_gemm128<<<dim3(NN / 128, NN / 128, HH), 256>>>(
        qp, kp, out_w, MM, NN, (long)NN * MM, (long)NN * MM, (long)NN * NN, 1.0f);

    ctx_kernel<<<dim3(4, 8, HH), 256>>>(kp, v, ctx);
    dinv_kernel<<<ROWS / 8, 256>>>(qp, ksum, dinv);
    out_kernel<<<dim3(NN / 64, HH), 256>>>(qp, ctx, dinv, out_align);
}

// round 3
// speedup vs baseline: 2.3127x; 2.3127x over previous
#include <cuda_runtime.h>
#include <math.h>
#include <stdint.h>

#define HH 16
#define NN 4096
#define DD 64
#define MM 256
#define ROWS (HH * NN)          // 65536

#define NORMALIZER 0.35355339059327373f  // 64^-0.25
#define DIAG_COEF  0.0625f               // 0.5 * 64^-0.5
#define RATIO      0.0625f               // 256^-0.5
#define FEPS       1e-4f

// ---------------- scratch (device globals; no allocation allowed) -------------
__device__ float g_qp[(size_t)ROWS * MM];
__device__ float g_kp[(size_t)ROWS * MM];
__device__ float g_qdiag[ROWS];
__device__ float g_kdiag[ROWS];
__device__ float g_ksum[HH * MM];
__device__ float g_dinv[ROWS];
__device__ float g_ctx[HH * MM * DD];
__device__ float g_kpart[1024];
__device__ float g_kmax[1];

__device__ __forceinline__ float to_tf32(float x) {
    uint32_t r;
    asm("cvt.rna.tf32.f32 %0, %1;" : "=r"(r) : "f"(x));
    return __uint_as_float(r);
}
__device__ __forceinline__ uint32_t smem_u32(const void* p) {
    uint32_t a;
    asm("{ .reg .u64 t; cvta.to.shared.u64 t, %1; cvt.u32.u64 %0, t; }" : "=r"(a) : "l"(p));
    return a;
}
__device__ __forceinline__ void cp_async16(uint32_t dst, const void* src) {
    asm volatile("cp.async.ca.shared.global [%0], [%1], 16;" :: "r"(dst), "l"(src) : "memory");
}
__device__ __forceinline__ void cp_commit() {
    asm volatile("cp.async.commit_group;" ::: "memory");
}
template <int N> __device__ __forceinline__ void cp_wait() {
    asm volatile("cp.async.wait_group %0;" :: "n"(N) : "memory");
}
__device__ __forceinline__ void mma_tf32_16x8x8(float* d, const uint32_t* a, const uint32_t* b) {
    asm volatile(
        "mma.sync.aligned.m16n8k8.row.col.f32.tf32.tf32.f32 "
        "{%0,%1,%2,%3}, {%4,%5,%6,%7}, {%8,%9}, {%0,%1,%2,%3};"
        : "+f"(d[0]), "+f"(d[1]), "+f"(d[2]), "+f"(d[3])
        : "r"(a[0]), "r"(a[1]), "r"(a[2]), "r"(a[3]), "r"(b[0]), "r"(b[1]));
}

// ---------------- zero accumulated scratch -------------------------------------
__global__ void zero_kernel() {
    int i = blockIdx.x * 256 + threadIdx.x;
    if (i < HH * MM) g_ksum[i] = 0.f;
    g_ctx[i] = 0.f;
}

// ---------------- generic NT SGEMM (feature projections) -----------------------
__global__ __launch_bounds__(256) void nt_gemm128(
    const float* __restrict__ A, const float* __restrict__ B, float* __restrict__ C,
    int K, int ldc, long sA, long sB, long sC, float alpha)
{
    A += (long)blockIdx.z * sA;
    B += (long)blockIdx.z * sB;
    C += (long)blockIdx.z * sC;
    const int i0 = blockIdx.x * 128;
    const int j0 = blockIdx.y * 128;

    __shared__ float As[16][132];
    __shared__ float Bs[16][132];

    const int t  = threadIdx.x;
    const int tx = t & 15;
    const int ty = t >> 4;

    float acc[8][8];
#pragma unroll
    for (int i = 0; i < 8; ++i)
#pragma unroll
        for (int j = 0; j < 8; ++j) acc[i][j] = 0.f;

    for (int k0 = 0; k0 < K; k0 += 16) {
#pragma unroll
        for (int l = 0; l < 2; ++l) {
            int idx = t + l * 256;
            int row = idx >> 2;
            int kq  = (idx & 3) << 2;
            float4 va = *(const float4*)(A + (long)(i0 + row) * K + k0 + kq);
            As[kq + 0][row] = va.x; As[kq + 1][row] = va.y;
            As[kq + 2][row] = va.z; As[kq + 3][row] = va.w;
            float4 vb = *(const float4*)(B + (long)(j0 + row) * K + k0 + kq);
            Bs[kq + 0][row] = vb.x; Bs[kq + 1][row] = vb.y;
            Bs[kq + 2][row] = vb.z; Bs[kq + 3][row] = vb.w;
        }
        __syncthreads();
#pragma unroll
        for (int k = 0; k < 16; ++k) {
            float4 a0 = *(const float4*)&As[k][ty * 4];
            float4 a1 = *(const float4*)&As[k][64 + ty * 4];
            float4 b0 = *(const float4*)&Bs[k][tx * 4];
            float4 b1 = *(const float4*)&Bs[k][64 + tx * 4];
            float a[8] = {a0.x, a0.y, a0.z, a0.w, a1.x, a1.y, a1.z, a1.w};
            float b[8] = {b0.x, b0.y, b0.z, b0.w, b1.x, b1.y, b1.z, b1.w};
#pragma unroll
            for (int i = 0; i < 8; ++i)
#pragma unroll
                for (int j = 0; j < 8; ++j)
                    acc[i][j] += a[i] * b[j];
        }
        __syncthreads();
    }

#pragma unroll
    for (int i = 0; i < 8; ++i) {
        int r = i0 + ((i < 4) ? (ty * 4 + i) : (64 + ty * 4 + i - 4));
        float* cp = C + (long)r * ldc + j0;
        float4 v0 = make_float4(acc[i][0] * alpha, acc[i][1] * alpha,
                                acc[i][2] * alpha, acc[i][3] * alpha);
        float4 v1 = make_float4(acc[i][4] * alpha, acc[i][5] * alpha,
                                acc[i][6] * alpha, acc[i][7] * alpha);
        *(float4*)(cp + tx * 4)      = v0;
        *(float4*)(cp + 64 + tx * 4) = v1;
    }
}

// ============ weights[h] = qp[h] @ kp[h]^T via mma.sync tf32 ===================
// 128x128 CTA tile, 8 warps (4x2), warp tile 32x64, K chunks of 32, cp.async
// double buffer. smem pad 36 floats/row -> conflict-free fragment loads.
#define WCHUNK   32
#define APITCH   36
#define ABUF_F   (128 * APITCH)                 // floats per buffer per operand
#define WT_SMEM  (4 * ABUF_F * 4)               // bytes: 2 ops x 2 bufs

__global__ __launch_bounds__(256) void weights_mma(
    const float* __restrict__ qp, const float* __restrict__ kp, float* __restrict__ outw)
{
    extern __shared__ float sm[];
    float* As = sm;                  // [2][128][36]
    float* Bs = sm + 2 * ABUF_F;     // [2][128][36]

    const int t    = threadIdx.x;
    const int lane = t & 31;
    const int w    = t >> 5;
    const int wm   = w & 3;          // 0..3  (M direction, 32 rows each)
    const int wn   = w >> 2;         // 0..1  (N direction, 64 cols each)
    const int grp  = lane >> 2;      // 0..7
    const int tig  = lane & 3;       // 0..3

    const int h  = blockIdx.z;
    const long i0 = (long)blockIdx.x * 128;
    const long j0 = (long)blockIdx.y * 128;

    const float* Ag = qp + ((long)h * NN + i0) * MM;
    const float* Bg = kp + ((long)h * NN + j0) * MM;

    // per-thread cp.async coords: 4 rows per operand, 16B each
    const int lrow = t >> 3;          // 0..31
    const int lcol = (t & 7) * 4;     // 0,4,...,28

    float acc[2][8][4];
#pragma unroll
    for (int mi = 0; mi < 2; ++mi)
#pragma unroll
        for (int ni = 0; ni < 8; ++ni)
#pragma unroll
            for (int r = 0; r < 4; ++r) acc[mi][ni][r] = 0.f;

    uint32_t As_u = smem_u32(As);
    uint32_t Bs_u = smem_u32(Bs);

    // prologue: chunk 0 -> buffer 0
#pragma unroll
    for (int i = 0; i < 4; ++i) {
        int row = i * 32 + lrow;
        cp_async16(As_u + (row * APITCH + lcol) * 4, Ag + (long)row * MM + lcol);
        cp_async16(Bs_u + (row * APITCH + lcol) * 4, Bg + (long)row * MM + lcol);
    }
    cp_commit();

#pragma unroll 1
    for (int c = 0; c < 8; ++c) {
        if (c < 7) {
            const int kof = (c + 1) * WCHUNK;
            const uint32_t ab = ((c + 1) & 1) * ABUF_F * 4;
#pragma unroll
            for (int i = 0; i < 4; ++i) {
                int row = i * 32 + lrow;
                cp_async16(As_u + ab + (row * APITCH + lcol) * 4, Ag + (long)row * MM + kof + lcol);
                cp_async16(Bs_u + ab + (row * APITCH + lcol) * 4, Bg + (long)row * MM + kof + lcol);
            }
            cp_commit();
            cp_wait<1>();
        } else {
            cp_wait<0>();
        }
        __syncthreads();

        const float* Ab = As + (c & 1) * ABUF_F;
        const float* Bb = Bs + (c & 1) * ABUF_F;

#pragma unroll
        for (int ks = 0; ks < 4; ++ks) {
            const int k0 = ks * 8;
            uint32_t a[2][4];
#pragma unroll
            for (int mi = 0; mi < 2; ++mi) {
                int m = wm * 32 + mi * 16 + grp;
                a[mi][0] = __float_as_uint(Ab[m * APITCH + k0 + tig]);
                a[mi][1] = __float_as_uint(Ab[(m + 8) * APITCH + k0 + tig]);
                a[mi][2] = __float_as_uint(Ab[m * APITCH + k0 + tig + 4]);
                a[mi][3] = __float_as_uint(Ab[(m + 8) * APITCH + k0 + tig + 4]);
            }
            uint32_t b[8][2];
#pragma unroll
            for (int ni = 0; ni < 8; ++ni) {
                int n = wn * 64 + ni * 8 + grp;
                b[ni][0] = __float_as_uint(Bb[n * APITCH + k0 + tig]);
                b[ni][1] = __float_as_uint(Bb[n * APITCH + k0 + tig + 4]);
            }
#pragma unroll
            for (int mi = 0; mi < 2; ++mi)
#pragma unroll
                for (int ni = 0; ni < 8; ++ni)
                    mma_tf32_16x8x8(acc[mi][ni], a[mi], b[ni]);
        }
        __syncthreads();
    }

    // epilogue: direct stores (float2 pairs; 32B sectors fully covered)
    float* Cp = outw + (long)h * NN * NN;
#pragma unroll
    for (int mi = 0; mi < 2; ++mi) {
        long row = i0 + wm * 32 + mi * 16 + grp;
#pragma unroll
        for (int ni = 0; ni < 8; ++ni) {
            long col = j0 + wn * 64 + ni * 8 + tig * 2;
            *(float2*)(Cp + row * NN + col)       = make_float2(acc[mi][ni][0], acc[mi][ni][1]);
            *(float2*)(Cp + (row + 8) * NN + col) = make_float2(acc[mi][ni][2], acc[mi][ni][3]);
        }
    }
}

// ---------------- diag[row] = DIAG_COEF * sum_d x[row][d]^2 -------------------
__global__ void diag_kernel(const float* __restrict__ x, float* __restrict__ out) {
    int row  = blockIdx.x * 8 + (threadIdx.x >> 5);
    int lane = threadIdx.x & 31;
    const float* p = x + (long)row * DD;
    float a = p[lane], b = p[lane + 32];
    float s = a * a + b * b;
#pragma unroll
    for (int o = 16; o; o >>= 1) s += __shfl_xor_sync(0xffffffffu, s, o);
    if (!lane) out[row] = s * DIAG_COEF;
}

// ---------------- global max over k dash (2-stage) -----------------------------
__global__ void kmax1_kernel(const float* __restrict__ d, float* __restrict__ part, int n) {
    float m = -3.4e38f;
    for (int i = blockIdx.x * blockDim.x + threadIdx.x; i < n; i += gridDim.x * blockDim.x)
        m = fmaxf(m, d[i]);
    __shared__ float sm[8];
#pragma unroll
    for (int o = 16; o; o >>= 1) m = fmaxf(m, __shfl_xor_sync(0xffffffffu, m, o));
    if ((threadIdx.x & 31) == 0) sm[threadIdx.x >> 5] = m;
    __syncthreads();
    if (threadIdx.x == 0) {
        float b = sm[0];
#pragma unroll
        for (int w = 1; w < 8; ++w) b = fmaxf(b, sm[w]);
        part[blockIdx.x] = b;
    }
}

__global__ void kmax2_kernel(const float* __restrict__ part, float* __restrict__ out, int n) {
    float m = -3.4e38f;
    for (int i = threadIdx.x; i < n; i += 256) m = fmaxf(m, part[i]);
    __shared__ float sm[8];
#pragma unroll
    for (int o = 16; o; o >>= 1) m = fmaxf(m, __shfl_xor_sync(0xffffffffu, m, o));
    if ((threadIdx.x & 31) == 0) sm[threadIdx.x >> 5] = m;
    __syncthreads();
    if (threadIdx.x == 0) {
        float b = sm[0];
#pragma unroll
        for (int w = 1; w < 8; ++w) b = fmaxf(b, sm[w]);
        out[0] = b;
    }
}

// ---------------- q features: per-row max, exp, tf32 round, in place -----------
__global__ void expq_kernel(float* __restrict__ dash, const float* __restrict__ diag) {
    long row = blockIdx.x;
    int  t   = threadIdx.x;
    long idx = row * MM + t;
    float x = dash[idx];
    float m = x;
#pragma unroll
    for (int o = 16; o; o >>= 1) m = fmaxf(m, __shfl_xor_sync(0xffffffffu, m, o));
    __shared__ float sm[8];
    if ((t & 31) == 0) sm[t >> 5] = m;
    __syncthreads();
    float bm = sm[0];
#pragma unroll
    for (int w = 1; w < 8; ++w) bm = fmaxf(bm, sm[w]);
    dash[idx] = to_tf32(RATIO * (expf(x - diag[row] - bm) + FEPS));
}

// ---------------- k features: global stab, exp, tf32 round, fused col sums -----
__global__ void expk_kernel(float* __restrict__ dash, const float* __restrict__ diag,
                            const float* __restrict__ kmax, float* __restrict__ ksum) {
    int t    = threadIdx.x;
    int row0 = blockIdx.x * 64;
    int h    = row0 >> 12;
    float stab  = kmax[0];
    float local = 0.f;
    for (int r = 0; r < 64; ++r) {
        long idx = (long)(row0 + r) * MM + t;
        float vv = to_tf32(RATIO * (expf(dash[idx] - diag[row0 + r] - stab) + FEPS));
        dash[idx] = vv;
        local += vv;
    }
    atomicAdd(&ksum[h * MM + t], local);
}

// ---------------- context[h][m][e] = sum_n kp[h][n][m] * v[h][n][e] -----------
__global__ __launch_bounds__(256) void ctx_kernel(const float* __restrict__ kp,
                                                  const float* __restrict__ v,
                                                  float* __restrict__ ctx) {
    int h  = blockIdx.z;
    int m0 = blockIdx.x * 64;
    int n0 = blockIdx.y * 512;
    __shared__ float kps[16][64];
    __shared__ float vs[16][64];
    int t  = threadIdx.x;
    int ti = t >> 4, tj = t & 15;
    int lr = t >> 4, lf = t & 15;
    float acc[4][4];
#pragma unroll
    for (int i = 0; i < 4; ++i)
#pragma unroll
        for (int j = 0; j < 4; ++j) acc[i][j] = 0.f;

    const float* kpb = kp + (long)h * NN * MM;
    const float* vb  = v  + (long)h * NN * DD;

    for (int nb = 0; nb < 32; ++nb) {
        int n = n0 + nb * 16 + lr;
        *(float4*)&kps[lr][lf * 4] = *(const float4*)(kpb + (long)n * MM + m0 + lf * 4);
        *(float4*)&vs[lr][lf * 4]  = *(const float4*)(vb  + (long)n * DD + lf * 4);
        __syncthreads();
#pragma unroll
        for (int nn = 0; nn < 16; ++nn) {
            float4 a4 = *(const float4*)&kps[nn][ti * 4];
            float4 b4 = *(const float4*)&vs[nn][tj * 4];
            float a[4] = {a4.x, a4.y, a4.z, a4.w};
            float b[4] = {b4.x, b4.y, b4.z, b4.w};
#pragma unroll
            for (int i = 0; i < 4; ++i)
#pragma unroll
                for (int j = 0; j < 4; ++j) acc[i][j] += a[i] * b[j];
        }
        __syncthreads();
    }
#pragma unroll
    for (int i = 0; i < 4; ++i)
#pragma unroll
        for (int j = 0; j < 4; ++j)
            atomicAdd(&ctx[((long)h * MM + m0 + ti * 4 + i) * DD + tj * 4 + j], acc[i][j]);
}

// ---------------- d_inv[row] = 1 / dot(qp[row], ksum[h]) ----------------------
__global__ void dinv_kernel(const float* __restrict__ qp, const float* __restrict__ ksum,
                            float* __restrict__ dinv) {
    int row  = blockIdx.x * 8 + (threadIdx.x >> 5);
    int lane = threadIdx.x & 31;
    int h    = row >> 12;
    const float* qr = qp + (long)row * MM;
    const float* ks = ksum + h * MM;
    float s = 0.f;
#pragma unroll
    for (int i = 0; i < 8; ++i) {
        int m = lane + i * 32;
        s += qr[m] * ks[m];
    }
#pragma unroll
    for (int o = 16; o; o >>= 1) s += __shfl_xor_sync(0xffffffffu, s, o);
    if (!lane) dinv[row] = 1.f / s;
}

// ---------------- out[h][n][e] = dinv * sum_m qp[h][n][m] * ctx[h][m][e] ------
__global__ __launch_bounds__(256) void out_kernel(const float* __restrict__ qp,
                                                  const float* __restrict__ ctx,
                                                  const float* __restrict__ dinv,
                                                  float* __restrict__ out) {
    int h  = blockIdx.y;
    int n0 = blockIdx.x * 64;
    __shared__ float qps[64][17];
    __shared__ float cs[16][64];
    int t  = threadIdx.x;
    int ti = t >> 4, tj = t & 15;
    float acc[4][4];
#pragma unroll
    for (int i = 0; i < 4; ++i)
#pragma unroll
        for (int j = 0; j < 4; ++j) acc[i][j] = 0.f;

    const float* qpb = qp + ((long)h * NN + n0) * MM;
    const float* cb  = ctx + (long)h * MM * DD;

    for (int mb = 0; mb < 16; ++mb) {
        {
            int r  = t >> 2;
            int cq = (t & 3) * 4;
            float4 vq = *(const float4*)(qpb + (long)r * MM + mb * 16 + cq);
            qps[r][cq + 0] = vq.x; qps[r][cq + 1] = vq.y;
            qps[r][cq + 2] = vq.z; qps[r][cq + 3] = vq.w;
        }
        {
            int mr = t >> 4, f = t & 15;
            *(float4*)&cs[mr][f * 4] = *(const float4*)(cb + (long)(mb * 16 + mr) * DD + f * 4);
        }
        __syncthreads();
#pragma unroll
        for (int k = 0; k < 16; ++k) {
            float a[4];
#pragma unroll
            for (int i = 0; i < 4; ++i) a[i] = qps[ti * 4 + i][k];
            float4 b4 = *(const float4*)&cs[k][tj * 4];
            float b[4] = {b4.x, b4.y, b4.z, b4.w};
#pragma unroll
            for (int i = 0; i < 4; ++i)
#pragma unroll
                for (int j = 0; j < 4; ++j) acc[i][j] += a[i] * b[j];
        }
        __syncthreads();
    }
#pragma unroll
    for (int i = 0; i < 4; ++i) {
        int n = n0 + ti * 4 + i;
        float dv = dinv[(long)h * NN + n];
        float4 o = make_float4(acc[i][0] * dv, acc[i][1] * dv, acc[i][2] * dv, acc[i][3] * dv);
        *(float4*)(out + ((long)h * NN + n) * DD + tj * 4) = o;
    }
}

// -------------------------------------------------------------------------------
extern "C" void kernel_launch(void* const* d_in, const int* in_sizes, int n_in,
                              void* d_out, int out_size)
{
    const float* q    = (const float*)d_in[0];
    const float* k    = (const float*)d_in[1];
    const float* v    = (const float*)d_in[2];
    const float* proj = (const float*)d_in[3];

    float* out_align = (float*)d_out;                       // [H,N,D]
    float* out_w     = out_align + (long)HH * NN * DD;      // [H,N,N]

    float *qp, *kp, *qdiag, *kdiag, *ksum, *dinv, *ctx, *kpart, *kmax;
    cudaGetSymbolAddress((void**)&qp,    g_qp);
    cudaGetSymbolAddress((void**)&kp,    g_kp);
    cudaGetSymbolAddress((void**)&qdiag, g_qdiag);
    cudaGetSymbolAddress((void**)&kdiag, g_kdiag);
    cudaGetSymbolAddress((void**)&ksum,  g_ksum);
    cudaGetSymbolAddress((void**)&dinv,  g_dinv);
    cudaGetSymbolAddress((void**)&ctx,   g_ctx);
    cudaGetSymbolAddress((void**)&kpart, g_kpart);
    cudaGetSymbolAddress((void**)&kmax,  g_kmax);

    cudaFuncSetAttribute(weights_mma, cudaFuncAttributeMaxDynamicSharedMemorySize, WT_SMEM);

    zero_kernel<<<HH * MM * DD / 256, 256>>>();

    nt_gemm128<<<dim3(ROWS / 128, MM / 128, 1), 256>>>(q, proj, qp, DD, MM, 0, 0, 0, NORMALIZER);
    nt_gemm128<<<dim3(ROWS / 128, MM / 128, 1), 256>>>(k, proj, kp, DD, MM, 0, 0, 0, NORMALIZER);

    diag_kernel<<<ROWS / 8, 256>>>(q, qdiag);
    diag_kernel<<<ROWS / 8, 256>>>(k, kdiag);

    kmax1_kernel<<<1024, 256>>>(kp, kpart, ROWS * MM);
    kmax2_kernel<<<1, 256>>>(kpart, kmax, 1024);

    expq_kernel<<<ROWS, 256>>>(qp, qdiag);
    expk_kernel<<<ROWS / 64, 256>>>(kp, kdiag, kmax, ksum);

    // dominant GEMM on tensor cores (tf32 mma.sync)
    weights_mma<<<dim3(NN / 128, NN / 128, HH), 256, WT_SMEM>>>(qp, kp, out_w);

    ctx_kernel<<<dim3(4, 8, HH), 256>>>(kp, v, ctx);
    dinv_kernel<<<ROWS / 8, 256>>>(qp, ksum, dinv);
    out_kernel<<<dim3(NN / 64, HH), 256>>>(qp, ctx, dinv, out_align);
}

// round 4
// speedup vs baseline: 2.5180x; 1.0888x over previous
#include <cuda_runtime.h>
#include <math.h>
#include <stdint.h>

#define HH 16
#define NN 4096
#define DD 64
#define MM 256
#define ROWS (HH * NN)          // 65536

#define NORMALIZER 0.35355339059327373f  // 64^-0.25
#define DIAG_COEF  0.0625f               // 0.5 * 64^-0.5
#define RATIO      0.0625f               // 256^-0.5
#define FEPS       1e-4f

// ---------------- scratch (device globals; no allocation allowed) -------------
__device__ float g_qp[(size_t)ROWS * MM];
__device__ float g_kp[(size_t)ROWS * MM];
__device__ float g_qdiag[ROWS];
__device__ float g_kdiag[ROWS];
__device__ float g_ksum[HH * MM];
__device__ float g_dinv[ROWS];
__device__ float g_ctx[HH * MM * DD];
__device__ float g_kpart[1024];
__device__ float g_kmax[1];

__device__ __forceinline__ float to_tf32(float x) {
    uint32_t r;
    asm("cvt.rna.tf32.f32 %0, %1;" : "=r"(r) : "f"(x));
    return __uint_as_float(r);
}
__device__ __forceinline__ uint32_t to_tf32_u(float x) {
    uint32_t r;
    asm("cvt.rna.tf32.f32 %0, %1;" : "=r"(r) : "f"(x));
    return r;
}
__device__ __forceinline__ uint32_t smem_u32(const void* p) {
    uint32_t a;
    asm("{ .reg .u64 t; cvta.to.shared.u64 t, %1; cvt.u32.u64 %0, t; }" : "=r"(a) : "l"(p));
    return a;
}
__device__ __forceinline__ void cp_async16(uint32_t dst, const void* src) {
    asm volatile("cp.async.ca.shared.global [%0], [%1], 16;" :: "r"(dst), "l"(src) : "memory");
}
__device__ __forceinline__ void cp_commit() {
    asm volatile("cp.async.commit_group;" ::: "memory");
}
template <int N> __device__ __forceinline__ void cp_wait() {
    asm volatile("cp.async.wait_group %0;" :: "n"(N) : "memory");
}
__device__ __forceinline__ void mma_tf32_16x8x8(float* d, const uint32_t* a, const uint32_t* b) {
    asm volatile(
        "mma.sync.aligned.m16n8k8.row.col.f32.tf32.tf32.f32 "
        "{%0,%1,%2,%3}, {%4,%5,%6,%7}, {%8,%9}, {%0,%1,%2,%3};"
        : "+f"(d[0]), "+f"(d[1]), "+f"(d[2]), "+f"(d[3])
        : "r"(a[0]), "r"(a[1]), "r"(a[2]), "r"(a[3]), "r"(b[0]), "r"(b[1]));
}

// ---------------- zero accumulated scratch -------------------------------------
__global__ void zero_kernel() {
    int i = blockIdx.x * 256 + threadIdx.x;
    if (i < HH * MM) g_ksum[i] = 0.f;
    g_ctx[i] = 0.f;
}

// ========== projections via 3xTF32 split: dash = alpha * X @ proj^T ===========
// C[128 rows x 128 m], K=64 in 2 chunks of 32. hi/lo split for fp32 accuracy.
#define PJ_PITCH 36
#define PJ_TILE  (128 * PJ_PITCH)
#define PJ_SMEM  (4 * PJ_TILE * 4)     // Ah, Al, Bh, Bl

__global__ __launch_bounds__(256) void proj_mma(
    const float* __restrict__ X, const float* __restrict__ P, float* __restrict__ C)
{
    extern __shared__ float sm[];
    float* Ah = sm;
    float* Al = sm + PJ_TILE;
    float* Bh = sm + 2 * PJ_TILE;
    float* Bl = sm + 3 * PJ_TILE;

    const int t    = threadIdx.x;
    const int lane = t & 31;
    const int w    = t >> 5;
    const int wm   = w & 3;
    const int wn   = w >> 2;
    const int grp  = lane >> 2;
    const int tig  = lane & 3;

    const long i0 = (long)blockIdx.x * 128;
    const int  j0 = blockIdx.y * 128;

    const int lrow = t >> 3;
    const int lcol = (t & 7) * 4;

    float acc[2][8][4];
#pragma unroll
    for (int mi = 0; mi < 2; ++mi)
#pragma unroll
        for (int ni = 0; ni < 8; ++ni)
#pragma unroll
            for (int r = 0; r < 4; ++r) acc[mi][ni][r] = 0.f;

#pragma unroll
    for (int c = 0; c < 2; ++c) {
        const int kof = c * 32;
#pragma unroll
        for (int i = 0; i < 4; ++i) {
            int row = i * 32 + lrow;
            float4 va = *(const float4*)(X + (i0 + row) * DD + kof + lcol);
            float4 vb = *(const float4*)(P + (long)(j0 + row) * DD + kof + lcol);
            float4 ah, al, bh, bl;
            ah.x = to_tf32(va.x); al.x = to_tf32(va.x - ah.x);
            ah.y = to_tf32(va.y); al.y = to_tf32(va.y - ah.y);
            ah.z = to_tf32(va.z); al.z = to_tf32(va.z - ah.z);
            ah.w = to_tf32(va.w); al.w = to_tf32(va.w - ah.w);
            bh.x = to_tf32(vb.x); bl.x = to_tf32(vb.x - bh.x);
            bh.y = to_tf32(vb.y); bl.y = to_tf32(vb.y - bh.y);
            bh.z = to_tf32(vb.z); bl.z = to_tf32(vb.z - bh.z);
            bh.w = to_tf32(vb.w); bl.w = to_tf32(vb.w - bh.w);
            *(float4*)&Ah[row * PJ_PITCH + lcol] = ah;
            *(float4*)&Al[row * PJ_PITCH + lcol] = al;
            *(float4*)&Bh[row * PJ_PITCH + lcol] = bh;
            *(float4*)&Bl[row * PJ_PITCH + lcol] = bl;
        }
        __syncthreads();

#pragma unroll
        for (int ks = 0; ks < 4; ++ks) {
            const int k0 = ks * 8;
            uint32_t ahr[2][4], alr[2][4];
#pragma unroll
            for (int mi = 0; mi < 2; ++mi) {
                int m = wm * 32 + mi * 16 + grp;
                ahr[mi][0] = __float_as_uint(Ah[m * PJ_PITCH + k0 + tig]);
                ahr[mi][1] = __float_as_uint(Ah[(m + 8) * PJ_PITCH + k0 + tig]);
                ahr[mi][2] = __float_as_uint(Ah[m * PJ_PITCH + k0 + tig + 4]);
                ahr[mi][3] = __float_as_uint(Ah[(m + 8) * PJ_PITCH + k0 + tig + 4]);
                alr[mi][0] = __float_as_uint(Al[m * PJ_PITCH + k0 + tig]);
                alr[mi][1] = __float_as_uint(Al[(m + 8) * PJ_PITCH + k0 + tig]);
                alr[mi][2] = __float_as_uint(Al[m * PJ_PITCH + k0 + tig + 4]);
                alr[mi][3] = __float_as_uint(Al[(m + 8) * PJ_PITCH + k0 + tig + 4]);
            }
#pragma unroll
            for (int ni = 0; ni < 8; ++ni) {
                int n = wn * 64 + ni * 8 + grp;
                uint32_t bhr[2], blr[2];
                bhr[0] = __float_as_uint(Bh[n * PJ_PITCH + k0 + tig]);
                bhr[1] = __float_as_uint(Bh[n * PJ_PITCH + k0 + tig + 4]);
                blr[0] = __float_as_uint(Bl[n * PJ_PITCH + k0 + tig]);
                blr[1] = __float_as_uint(Bl[n * PJ_PITCH + k0 + tig + 4]);
#pragma unroll
                for (int mi = 0; mi < 2; ++mi) {
                    mma_tf32_16x8x8(acc[mi][ni], ahr[mi], blr);
                    mma_tf32_16x8x8(acc[mi][ni], alr[mi], bhr);
                    mma_tf32_16x8x8(acc[mi][ni], ahr[mi], bhr);
                }
            }
        }
        __syncthreads();
    }

#pragma unroll
    for (int mi = 0; mi < 2; ++mi) {
        long row = i0 + wm * 32 + mi * 16 + grp;
#pragma unroll
        for (int ni = 0; ni < 8; ++ni) {
            long col = j0 + wn * 64 + ni * 8 + tig * 2;
            *(float2*)(C + row * MM + col) =
                make_float2(acc[mi][ni][0] * NORMALIZER, acc[mi][ni][1] * NORMALIZER);
            *(float2*)(C + (row + 8) * MM + col) =
                make_float2(acc[mi][ni][2] * NORMALIZER, acc[mi][ni][3] * NORMALIZER);
        }
    }
}

// ============ weights[h] = qp[h] @ kp[h]^T via mma.sync tf32 ===================
#define WCHUNK   32
#define APITCH   36
#define ABUF_F   (128 * APITCH)
#define WT_SMEM  (4 * ABUF_F * 4)

__global__ __launch_bounds__(256) void weights_mma(
    const float* __restrict__ qp, const float* __restrict__ kp, float* __restrict__ outw)
{
    extern __shared__ float sm[];
    float* As = sm;                  // [2][128][36]
    float* Bs = sm + 2 * ABUF_F;

    const int t    = threadIdx.x;
    const int lane = t & 31;
    const int w    = t >> 5;
    const int wm   = w & 3;
    const int wn   = w >> 2;
    const int grp  = lane >> 2;
    const int tig  = lane & 3;

    const int h  = blockIdx.z;
    const long i0 = (long)blockIdx.x * 128;
    const long j0 = (long)blockIdx.y * 128;

    const float* Ag = qp + ((long)h * NN + i0) * MM;
    const float* Bg = kp + ((long)h * NN + j0) * MM;

    const int lrow = t >> 3;
    const int lcol = (t & 7) * 4;

    float acc[2][8][4];
#pragma unroll
    for (int mi = 0; mi < 2; ++mi)
#pragma unroll
        for (int ni = 0; ni < 8; ++ni)
#pragma unroll
            for (int r = 0; r < 4; ++r) acc[mi][ni][r] = 0.f;

    uint32_t As_u = smem_u32(As);
    uint32_t Bs_u = smem_u32(Bs);

#pragma unroll
    for (int i = 0; i < 4; ++i) {
        int row = i * 32 + lrow;
        cp_async16(As_u + (row * APITCH + lcol) * 4, Ag + (long)row * MM + lcol);
        cp_async16(Bs_u + (row * APITCH + lcol) * 4, Bg + (long)row * MM + lcol);
    }
    cp_commit();

#pragma unroll 1
    for (int c = 0; c < 8; ++c) {
        cp_wait<0>();
        __syncthreads();
        if (c < 7) {
            const int kof = (c + 1) * WCHUNK;
            const uint32_t ab = ((c + 1) & 1) * ABUF_F * 4;
#pragma unroll
            for (int i = 0; i < 4; ++i) {
                int row = i * 32 + lrow;
                cp_async16(As_u + ab + (row * APITCH + lcol) * 4, Ag + (long)row * MM + kof + lcol);
                cp_async16(Bs_u + ab + (row * APITCH + lcol) * 4, Bg + (long)row * MM + kof + lcol);
            }
            cp_commit();
        }

        const float* Ab = As + (c & 1) * ABUF_F;
        const float* Bb = Bs + (c & 1) * ABUF_F;

#pragma unroll
        for (int ks = 0; ks < 4; ++ks) {
            const int k0 = ks * 8;
            uint32_t a[2][4];
#pragma unroll
            for (int mi = 0; mi < 2; ++mi) {
                int m = wm * 32 + mi * 16 + grp;
                a[mi][0] = __float_as_uint(Ab[m * APITCH + k0 + tig]);
                a[mi][1] = __float_as_uint(Ab[(m + 8) * APITCH + k0 + tig]);
                a[mi][2] = __float_as_uint(Ab[m * APITCH + k0 + tig + 4]);
                a[mi][3] = __float_as_uint(Ab[(m + 8) * APITCH + k0 + tig + 4]);
            }
            uint32_t b[8][2];
#pragma unroll
            for (int ni = 0; ni < 8; ++ni) {
                int n = wn * 64 + ni * 8 + grp;
                b[ni][0] = __float_as_uint(Bb[n * APITCH + k0 + tig]);
                b[ni][1] = __float_as_uint(Bb[n * APITCH + k0 + tig + 4]);
            }
#pragma unroll
            for (int mi = 0; mi < 2; ++mi)
#pragma unroll
                for (int ni = 0; ni < 8; ++ni)
                    mma_tf32_16x8x8(acc[mi][ni], a[mi], b[ni]);
        }
    }

    float* Cp = outw + (long)h * NN * NN;
#pragma unroll
    for (int mi = 0; mi < 2; ++mi) {
        long row = i0 + wm * 32 + mi * 16 + grp;
#pragma unroll
        for (int ni = 0; ni < 8; ++ni) {
            long col = j0 + wn * 64 + ni * 8 + tig * 2;
            *(float2*)(Cp + row * NN + col)       = make_float2(acc[mi][ni][0], acc[mi][ni][1]);
            *(float2*)(Cp + (row + 8) * NN + col) = make_float2(acc[mi][ni][2], acc[mi][ni][3]);
        }
    }
}

// ======= ctx[h][m][e] = sum_n kp[h][n][m] * v[h][n][e]  via mma tf32 ==========
// k-major smem tiles (no transpose): Ks[k][m] pitch 260, Vs[k][e] pitch 68.
#define CTX_KSPLIT 16
#define CTX_KC     32
#define KS_PITCH   260
#define VS_PITCH   68
#define KS_BUF     (CTX_KC * KS_PITCH)
#define VS_BUF     (CTX_KC * VS_PITCH)
#define CTX_SMEM   ((2 * KS_BUF + 2 * VS_BUF) * 4)

__global__ __launch_bounds__(256) void ctx_mma(
    const float* __restrict__ kp, const float* __restrict__ v, float* __restrict__ ctx)
{
    extern __shared__ float sm[];
    float* Ks = sm;                    // [2][32][260]
    float* Vs = sm + 2 * KS_BUF;       // [2][32][68]

    const int t    = threadIdx.x;
    const int lane = t & 31;
    const int w    = t >> 5;
    const int wm   = w & 3;            // m: 64 each
    const int we   = w >> 2;           // e: 32 each
    const int grp  = lane >> 2;
    const int tig  = lane & 3;

    const int h     = blockIdx.z;
    const int nbase = blockIdx.y * (NN / CTX_KSPLIT);   // 256 n's per CTA

    const float* Kg = kp + ((long)h * NN + nbase) * MM;
    const float* Vg = v  + ((long)h * NN + nbase) * DD;

    const int krow = t >> 3;
    const int c4   = t & 7;

    float acc[4][4][4];
#pragma unroll
    for (int mi = 0; mi < 4; ++mi)
#pragma unroll
        for (int ni = 0; ni < 4; ++ni)
#pragma unroll
            for (int r = 0; r < 4; ++r) acc[mi][ni][r] = 0.f;

    uint32_t Ks_u = smem_u32(Ks);
    uint32_t Vs_u = smem_u32(Vs);

    // prologue: chunk 0 -> buf 0
#pragma unroll
    for (int i = 0; i < 8; ++i)
        cp_async16(Ks_u + (krow * KS_PITCH + (c4 + i * 8) * 4) * 4,
                   Kg + (long)krow * MM + (c4 + i * 8) * 4);
#pragma unroll
    for (int i = 0; i < 2; ++i)
        cp_async16(Vs_u + (krow * VS_PITCH + (c4 + i * 8) * 4) * 4,
                   Vg + (long)krow * DD + (c4 + i * 8) * 4);
    cp_commit();

#pragma unroll 1
    for (int c = 0; c < 8; ++c) {
        cp_wait<0>();
        __syncthreads();
        if (c < 7) {
            const int nof = (c + 1) * CTX_KC;
            const uint32_t kb = ((c + 1) & 1) * KS_BUF * 4;
            const uint32_t vb = ((c + 1) & 1) * VS_BUF * 4;
#pragma unroll
            for (int i = 0; i < 8; ++i)
                cp_async16(Ks_u + kb + (krow * KS_PITCH + (c4 + i * 8) * 4) * 4,
                           Kg + (long)(nof + krow) * MM + (c4 + i * 8) * 4);
#pragma unroll
            for (int i = 0; i < 2; ++i)
                cp_async16(Vs_u + vb + (krow * VS_PITCH + (c4 + i * 8) * 4) * 4,
                           Vg + (long)(nof + krow) * DD + (c4 + i * 8) * 4);
            cp_commit();
        }

        const float* Kb = Ks + (c & 1) * KS_BUF;
        const float* Vb = Vs + (c & 1) * VS_BUF;

#pragma unroll
        for (int ks = 0; ks < 4; ++ks) {
            const int k0 = ks * 8;
            uint32_t a[4][4];
#pragma unroll
            for (int mi = 0; mi < 4; ++mi) {
                int m = wm * 64 + mi * 16 + grp;
                a[mi][0] = __float_as_uint(Kb[(k0 + tig) * KS_PITCH + m]);
                a[mi][1] = __float_as_uint(Kb[(k0 + tig) * KS_PITCH + m + 8]);
                a[mi][2] = __float_as_uint(Kb[(k0 + tig + 4) * KS_PITCH + m]);
                a[mi][3] = __float_as_uint(Kb[(k0 + tig + 4) * KS_PITCH + m + 8]);
            }
            uint32_t b[4][2];
#pragma unroll
            for (int ni = 0; ni < 4; ++ni) {
                int e = we * 32 + ni * 8 + grp;
                b[ni][0] = to_tf32_u(Vb[(k0 + tig) * VS_PITCH + e]);
                b[ni][1] = to_tf32_u(Vb[(k0 + tig + 4) * VS_PITCH + e]);
            }
#pragma unroll
            for (int mi = 0; mi < 4; ++mi)
#pragma unroll
                for (int ni = 0; ni < 4; ++ni)
                    mma_tf32_16x8x8(acc[mi][ni], a[mi], b[ni]);
        }
    }

#pragma unroll
    for (int mi = 0; mi < 4; ++mi) {
        int m = wm * 64 + mi * 16 + grp;
#pragma unroll
        for (int ni = 0; ni < 4; ++ni) {
            int e = we * 32 + ni * 8 + tig * 2;
            float* p0 = &ctx[((long)h * MM + m) * DD + e];
            float* p1 = &ctx[((long)h * MM + m + 8) * DD + e];
            atomicAdd(p0,     acc[mi][ni][0]);
            atomicAdd(p0 + 1, acc[mi][ni][1]);
            atomicAdd(p1,     acc[mi][ni][2]);
            atomicAdd(p1 + 1, acc[mi][ni][3]);
        }
    }
}

// ======= out[h][n][e] = dinv[n] * sum_m qp[h][n][m] * ctx[h][m][e]  (mma) =====
#define OQ_PITCH 36
#define OC_PITCH 68
#define OQ_BUF   (128 * OQ_PITCH)
#define OC_BUF   (32 * OC_PITCH)
#define OUT_SMEM ((2 * OQ_BUF + 2 * OC_BUF) * 4)

__global__ __launch_bounds__(256) void out_mma(
    const float* __restrict__ qp, const float* __restrict__ ctx,
    const float* __restrict__ dinv, float* __restrict__ out)
{
    extern __shared__ float sm[];
    float* Qs = sm;                    // [2][128][36]
    float* Cs = sm + 2 * OQ_BUF;       // [2][32][68]

    const int t    = threadIdx.x;
    const int lane = t & 31;
    const int w    = t >> 5;
    const int wn   = w & 3;            // n: 32 each
    const int we   = w >> 2;           // e: 32 each
    const int grp  = lane >> 2;
    const int tig  = lane & 3;

    const int h  = blockIdx.y;
    const long n0 = (long)blockIdx.x * 128;

    const float* Qg = qp  + ((long)h * NN + n0) * MM;
    const float* Cg = ctx + (long)h * MM * DD;

    const int lrow = t >> 3;
    const int lcol = (t & 7) * 4;
    const int crow = t >> 3;
    const int cc4  = t & 7;

    float acc[2][4][4];
#pragma unroll
    for (int mi = 0; mi < 2; ++mi)
#pragma unroll
        for (int ni = 0; ni < 4; ++ni)
#pragma unroll
            for (int r = 0; r < 4; ++r) acc[mi][ni][r] = 0.f;

    uint32_t Qs_u = smem_u32(Qs);
    uint32_t Cs_u = smem_u32(Cs);

#pragma unroll
    for (int i = 0; i < 4; ++i) {
        int row = i * 32 + lrow;
        cp_async16(Qs_u + (row * OQ_PITCH + lcol) * 4, Qg + (long)row * MM + lcol);
    }
#pragma unroll
    for (int i = 0; i < 2; ++i)
        cp_async16(Cs_u + (crow * OC_PITCH + (cc4 + i * 8) * 4) * 4,
                   Cg + (long)crow * DD + (cc4 + i * 8) * 4);
    cp_commit();

#pragma unroll 1
    for (int c = 0; c < 8; ++c) {
        cp_wait<0>();
        __syncthreads();
        if (c < 7) {
            const int kof = (c + 1) * 32;
            const uint32_t qb = ((c + 1) & 1) * OQ_BUF * 4;
            const uint32_t cb = ((c + 1) & 1) * OC_BUF * 4;
#pragma unroll
            for (int i = 0; i < 4; ++i) {
                int row = i * 32 + lrow;
                cp_async16(Qs_u + qb + (row * OQ_PITCH + lcol) * 4,
                           Qg + (long)row * MM + kof + lcol);
            }
#pragma unroll
            for (int i = 0; i < 2; ++i)
                cp_async16(Cs_u + cb + (crow * OC_PITCH + (cc4 + i * 8) * 4) * 4,
                           Cg + (long)(kof + crow) * DD + (cc4 + i * 8) * 4);
            cp_commit();
        }

        const float* Qb = Qs + (c & 1) * OQ_BUF;
        const float* Cb = Cs + (c & 1) * OC_BUF;

#pragma unroll
        for (int ks = 0; ks < 4; ++ks) {
            const int k0 = ks * 8;
            uint32_t a[2][4];
#pragma unroll
            for (int mi = 0; mi < 2; ++mi) {
                int n = wn * 32 + mi * 16 + grp;
                a[mi][0] = __float_as_uint(Qb[n * OQ_PITCH + k0 + tig]);
                a[mi][1] = __float_as_uint(Qb[(n + 8) * OQ_PITCH + k0 + tig]);
                a[mi][2] = __float_as_uint(Qb[n * OQ_PITCH + k0 + tig + 4]);
                a[mi][3] = __float_as_uint(Qb[(n + 8) * OQ_PITCH + k0 + tig + 4]);
            }
            uint32_t b[4][2];
#pragma unroll
            for (int ni = 0; ni < 4; ++ni) {
                int e = we * 32 + ni * 8 + grp;
                b[ni][0] = to_tf32_u(Cb[(k0 + tig) * OC_PITCH + e]);
                b[ni][1] = to_tf32_u(Cb[(k0 + tig + 4) * OC_PITCH + e]);
            }
#pragma unroll
            for (int mi = 0; mi < 2; ++mi)
#pragma unroll
                for (int ni = 0; ni < 4; ++ni)
                    mma_tf32_16x8x8(acc[mi][ni], a[mi], b[ni]);
        }
    }

#pragma unroll
    for (int mi = 0; mi < 2; ++mi) {
        long n = n0 + wn * 32 + mi * 16 + grp;
        float dv0 = dinv[(long)h * NN + n];
        float dv1 = dinv[(long)h * NN + n + 8];
#pragma unroll
        for (int ni = 0; ni < 4; ++ni) {
            int e = we * 32 + ni * 8 + tig * 2;
            *(float2*)(out + ((long)h * NN + n) * DD + e) =
                make_float2(acc[mi][ni][0] * dv0, acc[mi][ni][1] * dv0);
            *(float2*)(out + ((long)h * NN + n + 8) * DD + e) =
                make_float2(acc[mi][ni][2] * dv1, acc[mi][ni][3] * dv1);
        }
    }
}

// ---------------- diag / kmax / exp / dinv (unchanged) -------------------------
__global__ void diag_kernel(const float* __restrict__ x, float* __restrict__ out) {
    int row  = blockIdx.x * 8 + (threadIdx.x >> 5);
    int lane = threadIdx.x & 31;
    const float* p = x + (long)row * DD;
    float a = p[lane], b = p[lane + 32];
    float s = a * a + b * b;
#pragma unroll
    for (int o = 16; o; o >>= 1) s += __shfl_xor_sync(0xffffffffu, s, o);
    if (!lane) out[row] = s * DIAG_COEF;
}

__global__ void kmax1_kernel(const float* __restrict__ d, float* __restrict__ part, int n) {
    float m = -3.4e38f;
    for (int i = blockIdx.x * blockDim.x + threadIdx.x; i < n; i += gridDim.x * blockDim.x)
        m = fmaxf(m, d[i]);
    __shared__ float sm[8];
#pragma unroll
    for (int o = 16; o; o >>= 1) m = fmaxf(m, __shfl_xor_sync(0xffffffffu, m, o));
    if ((threadIdx.x & 31) == 0) sm[threadIdx.x >> 5] = m;
    __syncthreads();
    if (threadIdx.x == 0) {
        float b = sm[0];
#pragma unroll
        for (int w = 1; w < 8; ++w) b = fmaxf(b, sm[w]);
        part[blockIdx.x] = b;
    }
}

__global__ void kmax2_kernel(const float* __restrict__ part, float* __restrict__ out, int n) {
    float m = -3.4e38f;
    for (int i = threadIdx.x; i < n; i += 256) m = fmaxf(m, part[i]);
    __shared__ float sm[8];
#pragma unroll
    for (int o = 16; o; o >>= 1) m = fmaxf(m, __shfl_xor_sync(0xffffffffu, m, o));
    if ((threadIdx.x & 31) == 0) sm[threadIdx.x >> 5] = m;
    __syncthreads();
    if (threadIdx.x == 0) {
        float b = sm[0];
#pragma unroll
        for (int w = 1; w < 8; ++w) b = fmaxf(b, sm[w]);
        out[0] = b;
    }
}

__global__ void expq_kernel(float* __restrict__ dash, const float* __restrict__ diag) {
    long row = blockIdx.x;
    int  t   = threadIdx.x;
    long idx = row * MM + t;
    float x = dash[idx];
    float m = x;
#pragma unroll
    for (int o = 16; o; o >>= 1) m = fmaxf(m, __shfl_xor_sync(0xffffffffu, m, o));
    __shared__ float sm[8];
    if ((t & 31) == 0) sm[t >> 5] = m;
    __syncthreads();
    float bm = sm[0];
#pragma unroll
    for (int w = 1; w < 8; ++w) bm = fmaxf(bm, sm[w]);
    dash[idx] = to_tf32(RATIO * (expf(x - diag[row] - bm) + FEPS));
}

__global__ void expk_kernel(float* __restrict__ dash, const float* __restrict__ diag,
                            const float* __restrict__ kmax, float* __restrict__ ksum) {
    int t    = threadIdx.x;
    int row0 = blockIdx.x * 64;
    int h    = row0 >> 12;
    float stab  = kmax[0];
    float local = 0.f;
    for (int r = 0; r < 64; ++r) {
        long idx = (long)(row0 + r) * MM + t;
        float vv = to_tf32(RATIO * (expf(dash[idx] - diag[row0 + r] - stab) + FEPS));
        dash[idx] = vv;
        local += vv;
    }
    atomicAdd(&ksum[h * MM + t], local);
}

__global__ void dinv_kernel(const float* __restrict__ qp, const float* __restrict__ ksum,
                            float* __restrict__ dinv) {
    int row  = blockIdx.x * 8 + (threadIdx.x >> 5);
    int lane = threadIdx.x & 31;
    int h    = row >> 12;
    const float* qr = qp + (long)row * MM;
    const float* ks = ksum + h * MM;
    float s = 0.f;
#pragma unroll
    for (int i = 0; i < 8; ++i) {
        int m = lane + i * 32;
        s += qr[m] * ks[m];
    }
#pragma unroll
    for (int o = 16; o; o >>= 1) s += __shfl_xor_sync(0xffffffffu, s, o);
    if (!lane) dinv[row] = 1.f / s;
}

// -------------------------------------------------------------------------------
extern "C" void kernel_launch(void* const* d_in, const int* in_sizes, int n_in,
                              void* d_out, int out_size)
{
    const float* q    = (const float*)d_in[0];
    const float* k    = (const float*)d_in[1];
    const float* v    = (const float*)d_in[2];
    const float* proj = (const float*)d_in[3];

    float* out_align = (float*)d_out;                       // [H,N,D]
    float* out_w     = out_align + (long)HH * NN * DD;      // [H,N,N]

    float *qp, *kp, *qdiag, *kdiag, *ksum, *dinv, *ctx, *kpart, *kmax;
    cudaGetSymbolAddress((void**)&qp,    g_qp);
    cudaGetSymbolAddress((void**)&kp,    g_kp);
    cudaGetSymbolAddress((void**)&qdiag, g_qdiag);
    cudaGetSymbolAddress((void**)&kdiag, g_kdiag);
    cudaGetSymbolAddress((void**)&ksum,  g_ksum);
    cudaGetSymbolAddress((void**)&dinv,  g_dinv);
    cudaGetSymbolAddress((void**)&ctx,   g_ctx);
    cudaGetSymbolAddress((void**)&kpart, g_kpart);
    cudaGetSymbolAddress((void**)&kmax,  g_kmax);

    static bool attr_done = false;
    if (!attr_done) {
        cudaFuncSetAttribute(weights_mma, cudaFuncAttributeMaxDynamicSharedMemorySize, WT_SMEM);
        cudaFuncSetAttribute(proj_mma,    cudaFuncAttributeMaxDynamicSharedMemorySize, PJ_SMEM);
        cudaFuncSetAttribute(ctx_mma,     cudaFuncAttributeMaxDynamicSharedMemorySize, CTX_SMEM);
        cudaFuncSetAttribute(out_mma,     cudaFuncAttributeMaxDynamicSharedMemorySize, OUT_SMEM);
        attr_done = true;
    }

    zero_kernel<<<HH * MM * DD / 256, 256>>>();

    proj_mma<<<dim3(ROWS / 128, MM / 128), 256, PJ_SMEM>>>(q, proj, qp);
    proj_mma<<<dim3(ROWS / 128, MM / 128), 256, PJ_SMEM>>>(k, proj, kp);

    diag_kernel<<<ROWS / 8, 256>>>(q, qdiag);
    diag_kernel<<<ROWS / 8, 256>>>(k, kdiag);

    kmax1_kernel<<<1024, 256>>>(kp, kpart, ROWS * MM);
    kmax2_kernel<<<1, 256>>>(kpart, kmax, 1024);

    expq_kernel<<<ROWS, 256>>>(qp, qdiag);
    expk_kernel<<<ROWS / 64, 256>>>(kp, kdiag, kmax, ksum);

    weights_mma<<<dim3(NN / 128, NN / 128, HH), 256, WT_SMEM>>>(qp, kp, out_w);

    ctx_mma<<<dim3(1, CTX_KSPLIT, HH), 256, CTX_SMEM>>>(kp, v, ctx);
    dinv_kernel<<<ROWS / 8, 256>>>(qp, ksum, dinv);
    out_mma<<<dim3(NN / 128, HH), 256, OUT_SMEM>>>(qp, ctx, dinv, out_align);
}

// round 5
// speedup vs baseline: 2.5868x; 1.0273x over previous
#include <cuda_runtime.h>
#include <math.h>
#include <stdint.h>

#define HH 16
#define NN 4096
#define DD 64
#define MM 256
#define ROWS (HH * NN)          // 65536

#define NORMALIZER 0.35355339059327373f  // 64^-0.25
#define DIAG_COEF  0.0625f               // 0.5 * 64^-0.5
#define RATIO      0.0625f               // 256^-0.5
#define FEPS       1e-4f

// ---------------- scratch (device globals; no allocation allowed) -------------
__device__ float g_qp[(size_t)ROWS * MM];
__device__ float g_kp[(size_t)ROWS * MM];
__device__ float g_qdiag[ROWS];
__device__ float g_kdiag[ROWS];
__device__ float g_ksum[HH * MM];
__device__ float g_dinv[ROWS];
__device__ float g_ctx[HH * MM * DD];
__device__ float g_kpart[1024];
__device__ float g_kmax[1];

__device__ __forceinline__ float to_tf32(float x) {
    uint32_t r;
    asm("cvt.rna.tf32.f32 %0, %1;" : "=r"(r) : "f"(x));
    return __uint_as_float(r);
}
__device__ __forceinline__ uint32_t to_tf32_u(float x) {
    uint32_t r;
    asm("cvt.rna.tf32.f32 %0, %1;" : "=r"(r) : "f"(x));
    return r;
}
__device__ __forceinline__ uint32_t smem_u32(const void* p) {
    uint32_t a;
    asm("{ .reg .u64 t; cvta.to.shared.u64 t, %1; cvt.u32.u64 %0, t; }" : "=r"(a) : "l"(p));
    return a;
}
__device__ __forceinline__ void cp_async16(uint32_t dst, const void* src) {
    asm volatile("cp.async.ca.shared.global [%0], [%1], 16;" :: "r"(dst), "l"(src) : "memory");
}
__device__ __forceinline__ void cp_commit() {
    asm volatile("cp.async.commit_group;" ::: "memory");
}
template <int N> __device__ __forceinline__ void cp_wait() {
    asm volatile("cp.async.wait_group %0;" :: "n"(N) : "memory");
}
__device__ __forceinline__ void mma_tf32_16x8x8(float* d, const uint32_t* a, const uint32_t* b) {
    asm volatile(
        "mma.sync.aligned.m16n8k8.row.col.f32.tf32.tf32.f32 "
        "{%0,%1,%2,%3}, {%4,%5,%6,%7}, {%8,%9}, {%0,%1,%2,%3};"
        : "+f"(d[0]), "+f"(d[1]), "+f"(d[2]), "+f"(d[3])
        : "r"(a[0]), "r"(a[1]), "r"(a[2]), "r"(a[3]), "r"(b[0]), "r"(b[1]));
}

// ---------------- zero accumulated scratch -------------------------------------
__global__ void zero_kernel() {
    int i = blockIdx.x * 256 + threadIdx.x;
    if (i < HH * MM) g_ksum[i] = 0.f;
    g_ctx[i] = 0.f;
}

// ========== projections via 3xTF32 split: dash = alpha * X @ proj^T ===========
#define PJ_PITCH 36
#define PJ_TILE  (128 * PJ_PITCH)
#define PJ_SMEM  (4 * PJ_TILE * 4)     // Ah, Al, Bh, Bl

__global__ __launch_bounds__(256) void proj_mma(
    const float* __restrict__ X, const float* __restrict__ P, float* __restrict__ C)
{
    extern __shared__ float sm[];
    float* Ah = sm;
    float* Al = sm + PJ_TILE;
    float* Bh = sm + 2 * PJ_TILE;
    float* Bl = sm + 3 * PJ_TILE;

    const int t    = threadIdx.x;
    const int lane = t & 31;
    const int w    = t >> 5;
    const int wm   = w & 3;
    const int wn   = w >> 2;
    const int grp  = lane >> 2;
    const int tig  = lane & 3;

    const long i0 = (long)blockIdx.x * 128;
    const int  j0 = blockIdx.y * 128;

    const int lrow = t >> 3;
    const int lcol = (t & 7) * 4;

    float acc[2][8][4];
#pragma unroll
    for (int mi = 0; mi < 2; ++mi)
#pragma unroll
        for (int ni = 0; ni < 8; ++ni)
#pragma unroll
            for (int r = 0; r < 4; ++r) acc[mi][ni][r] = 0.f;

#pragma unroll
    for (int c = 0; c < 2; ++c) {
        const int kof = c * 32;
#pragma unroll
        for (int i = 0; i < 4; ++i) {
            int row = i * 32 + lrow;
            float4 va = *(const float4*)(X + (i0 + row) * DD + kof + lcol);
            float4 vb = *(const float4*)(P + (long)(j0 + row) * DD + kof + lcol);
            float4 ah, al, bh, bl;
            ah.x = to_tf32(va.x); al.x = to_tf32(va.x - ah.x);
            ah.y = to_tf32(va.y); al.y = to_tf32(va.y - ah.y);
            ah.z = to_tf32(va.z); al.z = to_tf32(va.z - ah.z);
            ah.w = to_tf32(va.w); al.w = to_tf32(va.w - ah.w);
            bh.x = to_tf32(vb.x); bl.x = to_tf32(vb.x - bh.x);
            bh.y = to_tf32(vb.y); bl.y = to_tf32(vb.y - bh.y);
            bh.z = to_tf32(vb.z); bl.z = to_tf32(vb.z - bh.z);
            bh.w = to_tf32(vb.w); bl.w = to_tf32(vb.w - bh.w);
            *(float4*)&Ah[row * PJ_PITCH + lcol] = ah;
            *(float4*)&Al[row * PJ_PITCH + lcol] = al;
            *(float4*)&Bh[row * PJ_PITCH + lcol] = bh;
            *(float4*)&Bl[row * PJ_PITCH + lcol] = bl;
        }
        __syncthreads();

#pragma unroll
        for (int ks = 0; ks < 4; ++ks) {
            const int k0 = ks * 8;
            uint32_t ahr[2][4], alr[2][4];
#pragma unroll
            for (int mi = 0; mi < 2; ++mi) {
                int m = wm * 32 + mi * 16 + grp;
                ahr[mi][0] = __float_as_uint(Ah[m * PJ_PITCH + k0 + tig]);
                ahr[mi][1] = __float_as_uint(Ah[(m + 8) * PJ_PITCH + k0 + tig]);
                ahr[mi][2] = __float_as_uint(Ah[m * PJ_PITCH + k0 + tig + 4]);
                ahr[mi][3] = __float_as_uint(Ah[(m + 8) * PJ_PITCH + k0 + tig + 4]);
                alr[mi][0] = __float_as_uint(Al[m * PJ_PITCH + k0 + tig]);
                alr[mi][1] = __float_as_uint(Al[(m + 8) * PJ_PITCH + k0 + tig]);
                alr[mi][2] = __float_as_uint(Al[m * PJ_PITCH + k0 + tig + 4]);
                alr[mi][3] = __float_as_uint(Al[(m + 8) * PJ_PITCH + k0 + tig + 4]);
            }
#pragma unroll
            for (int ni = 0; ni < 8; ++ni) {
                int n = wn * 64 + ni * 8 + grp;
                uint32_t bhr[2], blr[2];
                bhr[0] = __float_as_uint(Bh[n * PJ_PITCH + k0 + tig]);
                bhr[1] = __float_as_uint(Bh[n * PJ_PITCH + k0 + tig + 4]);
                blr[0] = __float_as_uint(Bl[n * PJ_PITCH + k0 + tig]);
                blr[1] = __float_as_uint(Bl[n * PJ_PITCH + k0 + tig + 4]);
#pragma unroll
                for (int mi = 0; mi < 2; ++mi) {
                    mma_tf32_16x8x8(acc[mi][ni], ahr[mi], blr);
                    mma_tf32_16x8x8(acc[mi][ni], alr[mi], bhr);
                    mma_tf32_16x8x8(acc[mi][ni], ahr[mi], bhr);
                }
            }
        }
        __syncthreads();
    }

#pragma unroll
    for (int mi = 0; mi < 2; ++mi) {
        long row = i0 + wm * 32 + mi * 16 + grp;
#pragma unroll
        for (int ni = 0; ni < 8; ++ni) {
            long col = j0 + wn * 64 + ni * 8 + tig * 2;
            *(float2*)(C + row * MM + col) =
                make_float2(acc[mi][ni][0] * NORMALIZER, acc[mi][ni][1] * NORMALIZER);
            *(float2*)(C + (row + 8) * MM + col) =
                make_float2(acc[mi][ni][2] * NORMALIZER, acc[mi][ni][3] * NORMALIZER);
        }
    }
}

// ============ weights[h] = qp[h] @ kp[h]^T via mma.sync tf32 ===================
// 256x128 CTA tile, 8 warps (4x2), warp tile 64x64. K=256 in 8 chunks of 32,
// cp.async double buffer. LDS/MMA = 1.0; L2 read amplification 32x+16x.
#define W2_PITCH 36
#define W2_ABUF  (256 * W2_PITCH)      // floats per A stage
#define W2_BBUF  (128 * W2_PITCH)      // floats per B stage
#define W2_SMEM  ((2 * W2_ABUF + 2 * W2_BBUF) * 4)   // 110592 B

__global__ __launch_bounds__(256) void weights_mma(
    const float* __restrict__ qp, const float* __restrict__ kp, float* __restrict__ outw)
{
    extern __shared__ float sm[];
    float* As = sm;                    // [2][256][36]
    float* Bs = sm + 2 * W2_ABUF;      // [2][128][36]

    const int t    = threadIdx.x;
    const int lane = t & 31;
    const int w    = t >> 5;
    const int wm   = w & 3;            // 4 warps in M (64 rows each)
    const int wn   = w >> 2;           // 2 warps in N (64 cols each)
    const int grp  = lane >> 2;
    const int tig  = lane & 3;

    const int h   = blockIdx.z;
    const long i0 = (long)blockIdx.y * 256;
    const long j0 = (long)blockIdx.x * 128;

    const float* Ag = qp + ((long)h * NN + i0) * MM;
    const float* Bg = kp + ((long)h * NN + j0) * MM;

    const int lrow = t >> 3;           // 0..31
    const int lcol = (t & 7) * 4;      // 0..28

    float acc[4][8][4];
#pragma unroll
    for (int mi = 0; mi < 4; ++mi)
#pragma unroll
        for (int ni = 0; ni < 8; ++ni)
#pragma unroll
            for (int r = 0; r < 4; ++r) acc[mi][ni][r] = 0.f;

    uint32_t As_u = smem_u32(As);
    uint32_t Bs_u = smem_u32(Bs);

    // prologue: chunk 0 -> buffer 0
#pragma unroll
    for (int i = 0; i < 8; ++i) {
        int row = i * 32 + lrow;
        cp_async16(As_u + (row * W2_PITCH + lcol) * 4, Ag + (long)row * MM + lcol);
    }
#pragma unroll
    for (int i = 0; i < 4; ++i) {
        int row = i * 32 + lrow;
        cp_async16(Bs_u + (row * W2_PITCH + lcol) * 4, Bg + (long)row * MM + lcol);
    }
    cp_commit();

#pragma unroll 1
    for (int c = 0; c < 8; ++c) {
        cp_wait<0>();
        __syncthreads();
        if (c < 7) {
            const int kof = (c + 1) * 32;
            const uint32_t ab = ((c + 1) & 1) * W2_ABUF * 4;
            const uint32_t bb = ((c + 1) & 1) * W2_BBUF * 4;
#pragma unroll
            for (int i = 0; i < 8; ++i) {
                int row = i * 32 + lrow;
                cp_async16(As_u + ab + (row * W2_PITCH + lcol) * 4,
                           Ag + (long)row * MM + kof + lcol);
            }
#pragma unroll
            for (int i = 0; i < 4; ++i) {
                int row = i * 32 + lrow;
                cp_async16(Bs_u + bb + (row * W2_PITCH + lcol) * 4,
                           Bg + (long)row * MM + kof + lcol);
            }
            cp_commit();
        }

        const float* Ab = As + (c & 1) * W2_ABUF;
        const float* Bb = Bs + (c & 1) * W2_BBUF;

#pragma unroll
        for (int ks = 0; ks < 4; ++ks) {
            const int k0 = ks * 8;
            uint32_t a[4][4];
#pragma unroll
            for (int mi = 0; mi < 4; ++mi) {
                int m = wm * 64 + mi * 16 + grp;
                a[mi][0] = __float_as_uint(Ab[m * W2_PITCH + k0 + tig]);
                a[mi][1] = __float_as_uint(Ab[(m + 8) * W2_PITCH + k0 + tig]);
                a[mi][2] = __float_as_uint(Ab[m * W2_PITCH + k0 + tig + 4]);
                a[mi][3] = __float_as_uint(Ab[(m + 8) * W2_PITCH + k0 + tig + 4]);
            }
            uint32_t b[8][2];
#pragma unroll
            for (int ni = 0; ni < 8; ++ni) {
                int n = wn * 64 + ni * 8 + grp;
                b[ni][0] = __float_as_uint(Bb[n * W2_PITCH + k0 + tig]);
                b[ni][1] = __float_as_uint(Bb[n * W2_PITCH + k0 + tig + 4]);
            }
#pragma unroll
            for (int mi = 0; mi < 4; ++mi)
#pragma unroll
                for (int ni = 0; ni < 8; ++ni)
                    mma_tf32_16x8x8(acc[mi][ni], a[mi], b[ni]);
        }
    }

    float* Cp = outw + (long)h * NN * NN;
#pragma unroll
    for (int mi = 0; mi < 4; ++mi) {
        long row = i0 + wm * 64 + mi * 16 + grp;
#pragma unroll
        for (int ni = 0; ni < 8; ++ni) {
            long col = j0 + wn * 64 + ni * 8 + tig * 2;
            *(float2*)(Cp + row * NN + col)       = make_float2(acc[mi][ni][0], acc[mi][ni][1]);
            *(float2*)(Cp + (row + 8) * NN + col) = make_float2(acc[mi][ni][2], acc[mi][ni][3]);
        }
    }
}

// ======= ctx[h][m][e] = sum_n kp[h][n][m] * v[h][n][e]  via mma tf32 ==========
#define CTX_KSPLIT 16
#define CTX_KC     32
#define KS_PITCH   260
#define VS_PITCH   68
#define KS_BUF     (CTX_KC * KS_PITCH)
#define VS_BUF     (CTX_KC * VS_PITCH)
#define CTX_SMEM   ((2 * KS_BUF + 2 * VS_BUF) * 4)

__global__ __launch_bounds__(256) void ctx_mma(
    const float* __restrict__ kp, const float* __restrict__ v, float* __restrict__ ctx)
{
    extern __shared__ float sm[];
    float* Ks = sm;                    // [2][32][260]
    float* Vs = sm + 2 * KS_BUF;       // [2][32][68]

    const int t    = threadIdx.x;
    const int lane = t & 31;
    const int w    = t >> 5;
    const int wm   = w & 3;
    const int we   = w >> 2;
    const int grp  = lane >> 2;
    const int tig  = lane & 3;

    const int h     = blockIdx.z;
    const int nbase = blockIdx.y * (NN / CTX_KSPLIT);

    const float* Kg = kp + ((long)h * NN + nbase) * MM;
    const float* Vg = v  + ((long)h * NN + nbase) * DD;

    const int krow = t >> 3;
    const int c4   = t & 7;

    float acc[4][4][4];
#pragma unroll
    for (int mi = 0; mi < 4; ++mi)
#pragma unroll
        for (int ni = 0; ni < 4; ++ni)
#pragma unroll
            for (int r = 0; r < 4; ++r) acc[mi][ni][r] = 0.f;

    uint32_t Ks_u = smem_u32(Ks);
    uint32_t Vs_u = smem_u32(Vs);

#pragma unroll
    for (int i = 0; i < 8; ++i)
        cp_async16(Ks_u + (krow * KS_PITCH + (c4 + i * 8) * 4) * 4,
                   Kg + (long)krow * MM + (c4 + i * 8) * 4);
#pragma unroll
    for (int i = 0; i < 2; ++i)
        cp_async16(Vs_u + (krow * VS_PITCH + (c4 + i * 8) * 4) * 4,
                   Vg + (long)krow * DD + (c4 + i * 8) * 4);
    cp_commit();

#pragma unroll 1
    for (int c = 0; c < 8; ++c) {
        cp_wait<0>();
        __syncthreads();
        if (c < 7) {
            const int nof = (c + 1) * CTX_KC;
            const uint32_t kb = ((c + 1) & 1) * KS_BUF * 4;
            const uint32_t vb = ((c + 1) & 1) * VS_BUF * 4;
#pragma unroll
            for (int i = 0; i < 8; ++i)
                cp_async16(Ks_u + kb + (krow * KS_PITCH + (c4 + i * 8) * 4) * 4,
                           Kg + (long)(nof + krow) * MM + (c4 + i * 8) * 4);
#pragma unroll
            for (int i = 0; i < 2; ++i)
                cp_async16(Vs_u + vb + (krow * VS_PITCH + (c4 + i * 8) * 4) * 4,
                           Vg + (long)(nof + krow) * DD + (c4 + i * 8) * 4);
            cp_commit();
        }

        const float* Kb = Ks + (c & 1) * KS_BUF;
        const float* Vb = Vs + (c & 1) * VS_BUF;

#pragma unroll
        for (int ks = 0; ks < 4; ++ks) {
            const int k0 = ks * 8;
            uint32_t a[4][4];
#pragma unroll
            for (int mi = 0; mi < 4; ++mi) {
                int m = wm * 64 + mi * 16 + grp;
                a[mi][0] = __float_as_uint(Kb[(k0 + tig) * KS_PITCH + m]);
                a[mi][1] = __float_as_uint(Kb[(k0 + tig) * KS_PITCH + m + 8]);
                a[mi][2] = __float_as_uint(Kb[(k0 + tig + 4) * KS_PITCH + m]);
                a[mi][3] = __float_as_uint(Kb[(k0 + tig + 4) * KS_PITCH + m + 8]);
            }
            uint32_t b[4][2];
#pragma unroll
            for (int ni = 0; ni < 4; ++ni) {
                int e = we * 32 + ni * 8 + grp;
                b[ni][0] = to_tf32_u(Vb[(k0 + tig) * VS_PITCH + e]);
                b[ni][1] = to_tf32_u(Vb[(k0 + tig + 4) * VS_PITCH + e]);
            }
#pragma unroll
            for (int mi = 0; mi < 4; ++mi)
#pragma unroll
                for (int ni = 0; ni < 4; ++ni)
                    mma_tf32_16x8x8(acc[mi][ni], a[mi], b[ni]);
        }
    }

#pragma unroll
    for (int mi = 0; mi < 4; ++mi) {
        int m = wm * 64 + mi * 16 + grp;
#pragma unroll
        for (int ni = 0; ni < 4; ++ni) {
            int e = we * 32 + ni * 8 + tig * 2;
            float* p0 = &ctx[((long)h * MM + m) * DD + e];
            float* p1 = &ctx[((long)h * MM + m + 8) * DD + e];
            atomicAdd(p0,     acc[mi][ni][0]);
            atomicAdd(p0 + 1, acc[mi][ni][1]);
            atomicAdd(p1,     acc[mi][ni][2]);
            atomicAdd(p1 + 1, acc[mi][ni][3]);
        }
    }
}

// ======= out[h][n][e] = dinv[n] * sum_m qp[h][n][m] * ctx[h][m][e]  (mma) =====
#define OQ_PITCH 36
#define OC_PITCH 68
#define OQ_BUF   (128 * OQ_PITCH)
#define OC_BUF   (32 * OC_PITCH)
#define OUT_SMEM ((2 * OQ_BUF + 2 * OC_BUF) * 4)

__global__ __launch_bounds__(256) void out_mma(
    const float* __restrict__ qp, const float* __restrict__ ctx,
    const float* __restrict__ dinv, float* __restrict__ out)
{
    extern __shared__ float sm[];
    float* Qs = sm;                    // [2][128][36]
    float* Cs = sm + 2 * OQ_BUF;       // [2][32][68]

    const int t    = threadIdx.x;
    const int lane = t & 31;
    const int w    = t >> 5;
    const int wn   = w & 3;
    const int we   = w >> 2;
    const int grp  = lane >> 2;
    const int tig  = lane & 3;

    const int h  = blockIdx.y;
    const long n0 = (long)blockIdx.x * 128;

    const float* Qg = qp  + ((long)h * NN + n0) * MM;
    const float* Cg = ctx + (long)h * MM * DD;

    const int lrow = t >> 3;
    const int lcol = (t & 7) * 4;
    const int crow = t >> 3;
    const int cc4  = t & 7;

    float acc[2][4][4];
#pragma unroll
    for (int mi = 0; mi < 2; ++mi)
#pragma unroll
        for (int ni = 0; ni < 4; ++ni)
#pragma unroll
            for (int r = 0; r < 4; ++r) acc[mi][ni][r] = 0.f;

    uint32_t Qs_u = smem_u32(Qs);
    uint32_t Cs_u = smem_u32(Cs);

#pragma unroll
    for (int i = 0; i < 4; ++i) {
        int row = i * 32 + lrow;
        cp_async16(Qs_u + (row * OQ_PITCH + lcol) * 4, Qg + (long)row * MM + lcol);
    }
#pragma unroll
    for (int i = 0; i < 2; ++i)
        cp_async16(Cs_u + (crow * OC_PITCH + (cc4 + i * 8) * 4) * 4,
                   Cg + (long)crow * DD + (cc4 + i * 8) * 4);
    cp_commit();

#pragma unroll 1
    for (int c = 0; c < 8; ++c) {
        cp_wait<0>();
        __syncthreads();
        if (c < 7) {
            const int kof = (c + 1) * 32;
            const uint32_t qb = ((c + 1) & 1) * OQ_BUF * 4;
            const uint32_t cb = ((c + 1) & 1) * OC_BUF * 4;
#pragma unroll
            for (int i = 0; i < 4; ++i) {
                int row = i * 32 + lrow;
                cp_async16(Qs_u + qb + (row * OQ_PITCH + lcol) * 4,
                           Qg + (long)row * MM + kof + lcol);
            }
#pragma unroll
            for (int i = 0; i < 2; ++i)
                cp_async16(Cs_u + cb + (crow * OC_PITCH + (cc4 + i * 8) * 4) * 4,
                           Cg + (long)(kof + crow) * DD + (cc4 + i * 8) * 4);
            cp_commit();
        }

        const float* Qb = Qs + (c & 1) * OQ_BUF;
        const float* Cb = Cs + (c & 1) * OC_BUF;

#pragma unroll
        for (int ks = 0; ks < 4; ++ks) {
            const int k0 = ks * 8;
            uint32_t a[2][4];
#pragma unroll
            for (int mi = 0; mi < 2; ++mi) {
                int n = wn * 32 + mi * 16 + grp;
                a[mi][0] = __float_as_uint(Qb[n * OQ_PITCH + k0 + tig]);
                a[mi][1] = __float_as_uint(Qb[(n + 8) * OQ_PITCH + k0 + tig]);
                a[mi][2] = __float_as_uint(Qb[n * OQ_PITCH + k0 + tig + 4]);
                a[mi][3] = __float_as_uint(Qb[(n + 8) * OQ_PITCH + k0 + tig + 4]);
            }
            uint32_t b[4][2];
#pragma unroll
            for (int ni = 0; ni < 4; ++ni) {
                int e = we * 32 + ni * 8 + grp;
                b[ni][0] = to_tf32_u(Cb[(k0 + tig) * OC_PITCH + e]);
                b[ni][1] = to_tf32_u(Cb[(k0 + tig + 4) * OC_PITCH + e]);
            }
#pragma unroll
            for (int mi = 0; mi < 2; ++mi)
#pragma unroll
                for (int ni = 0; ni < 4; ++ni)
                    mma_tf32_16x8x8(acc[mi][ni], a[mi], b[ni]);
        }
    }

#pragma unroll
    for (int mi = 0; mi < 2; ++mi) {
        long n = n0 + wn * 32 + mi * 16 + grp;
        float dv0 = dinv[(long)h * NN + n];
        float dv1 = dinv[(long)h * NN + n + 8];
#pragma unroll
        for (int ni = 0; ni < 4; ++ni) {
            int e = we * 32 + ni * 8 + tig * 2;
            *(float2*)(out + ((long)h * NN + n) * DD + e) =
                make_float2(acc[mi][ni][0] * dv0, acc[mi][ni][1] * dv0);
            *(float2*)(out + ((long)h * NN + n + 8) * DD + e) =
                make_float2(acc[mi][ni][2] * dv1, acc[mi][ni][3] * dv1);
        }
    }
}

// ---------------- diag / kmax / exp / dinv -------------------------------------
__global__ void diag_kernel(const float* __restrict__ x, float* __restrict__ out) {
    int row  = blockIdx.x * 8 + (threadIdx.x >> 5);
    int lane = threadIdx.x & 31;
    const float* p = x + (long)row * DD;
    float a = p[lane], b = p[lane + 32];
    float s = a * a + b * b;
#pragma unroll
    for (int o = 16; o; o >>= 1) s += __shfl_xor_sync(0xffffffffu, s, o);
    if (!lane) out[row] = s * DIAG_COEF;
}

__global__ void kmax1_kernel(const float* __restrict__ d, float* __restrict__ part, int n) {
    float m = -3.4e38f;
    for (int i = blockIdx.x * blockDim.x + threadIdx.x; i < n; i += gridDim.x * blockDim.x)
        m = fmaxf(m, d[i]);
    __shared__ float sm[8];
#pragma unroll
    for (int o = 16; o; o >>= 1) m = fmaxf(m, __shfl_xor_sync(0xffffffffu, m, o));
    if ((threadIdx.x & 31) == 0) sm[threadIdx.x >> 5] = m;
    __syncthreads();
    if (threadIdx.x == 0) {
        float b = sm[0];
#pragma unroll
        for (int w = 1; w < 8; ++w) b = fmaxf(b, sm[w]);
        part[blockIdx.x] = b;
    }
}

__global__ void kmax2_kernel(const float* __restrict__ part, float* __restrict__ out, int n) {
    float m = -3.4e38f;
    for (int i = threadIdx.x; i < n; i += 256) m = fmaxf(m, part[i]);
    __shared__ float sm[8];
#pragma unroll
    for (int o = 16; o; o >>= 1) m = fmaxf(m, __shfl_xor_sync(0xffffffffu, m, o));
    if ((threadIdx.x & 31) == 0) sm[threadIdx.x >> 5] = m;
    __syncthreads();
    if (threadIdx.x == 0) {
        float b = sm[0];
#pragma unroll
        for (int w = 1; w < 8; ++w) b = fmaxf(b, sm[w]);
        out[0] = b;
    }
}

__global__ void expq_kernel(float* __restrict__ dash, const float* __restrict__ diag) {
    long row = blockIdx.x;
    int  t   = threadIdx.x;
    long idx = row * MM + t;
    float x = dash[idx];
    float m = x;
#pragma unroll
    for (int o = 16; o; o >>= 1) m = fmaxf(m, __shfl_xor_sync(0xffffffffu, m, o));
    __shared__ float sm[8];
    if ((t & 31) == 0) sm[t >> 5] = m;
    __syncthreads();
    float bm = sm[0];
#pragma unroll
    for (int w = 1; w < 8; ++w) bm = fmaxf(bm, sm[w]);
    dash[idx] = to_tf32(RATIO * (expf(x - diag[row] - bm) + FEPS));
}

__global__ void expk_kernel(float* __restrict__ dash, const float* __restrict__ diag,
                            const float* __restrict__ kmax, float* __restrict__ ksum) {
    int t    = threadIdx.x;
    int row0 = blockIdx.x * 64;
    int h    = row0 >> 12;
    float stab  = kmax[0];
    float local = 0.f;
    for (int r = 0; r < 64; ++r) {
        long idx = (long)(row0 + r) * MM + t;
        float vv = to_tf32(RATIO * (expf(dash[idx] - diag[row0 + r] - stab) + FEPS));
        dash[idx] = vv;
        local += vv;
    }
    atomicAdd(&ksum[h * MM + t], local);
}

__global__ void dinv_kernel(const float* __restrict__ qp, const float* __restrict__ ksum,
                            float* __restrict__ dinv) {
    int row  = blockIdx.x * 8 + (threadIdx.x >> 5);
    int lane = threadIdx.x & 31;
    int h    = row >> 12;
    const float* qr = qp + (long)row * MM;
    const float* ks = ksum + h * MM;
    float s = 0.f;
#pragma unroll
    for (int i = 0; i < 8; ++i) {
        int m = lane + i * 32;
        s += qr[m] * ks[m];
    }
#pragma unroll
    for (int o = 16; o; o >>= 1) s += __shfl_xor_sync(0xffffffffu, s, o);
    if (!lane) dinv[row] = 1.f / s;
}

// -------------------------------------------------------------------------------
extern "C" void kernel_launch(void* const* d_in, const int* in_sizes, int n_in,
                              void* d_out, int out_size)
{
    const float* q    = (const float*)d_in[0];
    const float* k    = (const float*)d_in[1];
    const float* v    = (const float*)d_in[2];
    const float* proj = (const float*)d_in[3];

    float* out_align = (float*)d_out;                       // [H,N,D]
    float* out_w     = out_align + (long)HH * NN * DD;      // [H,N,N]

    float *qp, *kp, *qdiag, *kdiag, *ksum, *dinv, *ctx, *kpart, *kmax;
    cudaGetSymbolAddress((void**)&qp,    g_qp);
    cudaGetSymbolAddress((void**)&kp,    g_kp);
    cudaGetSymbolAddress((void**)&qdiag, g_qdiag);
    cudaGetSymbolAddress((void**)&kdiag, g_kdiag);
    cudaGetSymbolAddress((void**)&ksum,  g_ksum);
    cudaGetSymbolAddress((void**)&dinv,  g_dinv);
    cudaGetSymbolAddress((void**)&ctx,   g_ctx);
    cudaGetSymbolAddress((void**)&kpart, g_kpart);
    cudaGetSymbolAddress((void**)&kmax,  g_kmax);

    static bool attr_done = false;
    if (!attr_done) {
        cudaFuncSetAttribute(weights_mma, cudaFuncAttributeMaxDynamicSharedMemorySize, W2_SMEM);
        cudaFuncSetAttribute(proj_mma,    cudaFuncAttributeMaxDynamicSharedMemorySize, PJ_SMEM);
        cudaFuncSetAttribute(ctx_mma,     cudaFuncAttributeMaxDynamicSharedMemorySize, CTX_SMEM);
        cudaFuncSetAttribute(out_mma,     cudaFuncAttributeMaxDynamicSharedMemorySize, OUT_SMEM);
        attr_done = true;
    }

    zero_kernel<<<HH * MM * DD / 256, 256>>>();

    proj_mma<<<dim3(ROWS / 128, MM / 128), 256, PJ_SMEM>>>(q, proj, qp);
    proj_mma<<<dim3(ROWS / 128, MM / 128), 256, PJ_SMEM>>>(k, proj, kp);

    diag_kernel<<<ROWS / 8, 256>>>(q, qdiag);
    diag_kernel<<<ROWS / 8, 256>>>(k, kdiag);

    kmax1_kernel<<<1024, 256>>>(kp, kpart, ROWS * MM);
    kmax2_kernel<<<1, 256>>>(kpart, kmax, 1024);

    expq_kernel<<<ROWS, 256>>>(qp, qdiag);
    expk_kernel<<<ROWS / 64, 256>>>(kp, kdiag, kmax, ksum);

    // dominant GEMM: 256x128 CTA tiles
    weights_mma<<<dim3(NN / 128, NN / 256, HH), 256, W2_SMEM>>>(qp, kp, out_w);

    ctx_mma<<<dim3(1, CTX_KSPLIT, HH), 256, CTX_SMEM>>>(kp, v, ctx);
    dinv_kernel<<<ROWS / 8, 256>>>(qp, ksum, dinv);
    out_mma<<<dim3(NN / 128, HH), 256, OUT_SMEM>>>(qp, ctx, dinv, out_align);
}

// round 7
// speedup vs baseline: 3.1913x; 1.2337x over previous
#include <cuda_runtime.h>
#include <cuda_fp16.h>
#include <math.h>
#include <stdint.h>

#define HH 16
#define NN 4096
#define DD 64
#define MM 256
#define ROWS (HH * NN)          // 65536

#define NORMALIZER 0.35355339059327373f  // 64^-0.25
#define DIAG_COEF  0.0625f               // 0.5 * 64^-0.5
#define RATIO      0.0625f               // 256^-0.5
#define FEPS       1e-4f
#define HSCALE     2048.0f               // lift fp16 features out of subnormals
#define HUNSCALE   (1.0f / 4194304.0f)   // 2^-22

// ---------------- scratch (device globals; no allocation allowed) -------------
__device__ float  g_qp[(size_t)ROWS * MM];
__device__ float  g_kp[(size_t)ROWS * MM];
__device__ __half g_qph[(size_t)ROWS * MM];
__device__ __half g_kph[(size_t)ROWS * MM];
__device__ float  g_qdiag[ROWS];
__device__ float  g_kdiag[ROWS];
__device__ float  g_ksum[HH * MM];
__device__ float  g_dinv[ROWS];
__device__ float  g_ctx[HH * MM * DD];
__device__ float  g_kpart[1024];
__device__ float  g_kmax[1];

__device__ __forceinline__ float to_tf32(float x) {
    uint32_t r;
    asm("cvt.rna.tf32.f32 %0, %1;" : "=r"(r) : "f"(x));
    return __uint_as_float(r);
}
__device__ __forceinline__ uint32_t to_tf32_u(float x) {
    uint32_t r;
    asm("cvt.rna.tf32.f32 %0, %1;" : "=r"(r) : "f"(x));
    return r;
}
__device__ __forceinline__ uint32_t smem_u32(const void* p) {
    uint32_t a;
    asm("{ .reg .u64 t; cvta.to.shared.u64 t, %1; cvt.u32.u64 %0, t; }" : "=r"(a) : "l"(p));
    return a;
}
__device__ __forceinline__ void cp_async16(uint32_t dst, const void* src) {
    asm volatile("cp.async.ca.shared.global [%0], [%1], 16;" :: "r"(dst), "l"(src) : "memory");
}
__device__ __forceinline__ void cp_commit() {
    asm volatile("cp.async.commit_group;" ::: "memory");
}
template <int N> __device__ __forceinline__ void cp_wait() {
    asm volatile("cp.async.wait_group %0;" :: "n"(N) : "memory");
}
__device__ __forceinline__ void mma_tf32_16x8x8(float* d, const uint32_t* a, const uint32_t* b) {
    asm volatile(
        "mma.sync.aligned.m16n8k8.row.col.f32.tf32.tf32.f32 "
        "{%0,%1,%2,%3}, {%4,%5,%6,%7}, {%8,%9}, {%0,%1,%2,%3};"
        : "+f"(d[0]), "+f"(d[1]), "+f"(d[2]), "+f"(d[3])
        : "r"(a[0]), "r"(a[1]), "r"(a[2]), "r"(a[3]), "r"(b[0]), "r"(b[1]));
}
__device__ __forceinline__ void mma_f16_16x8x16(float* d, const uint32_t* a, const uint32_t* b) {
    asm volatile(
        "mma.sync.aligned.m16n8k16.row.col.f32.f16.f16.f32 "
        "{%0,%1,%2,%3}, {%4,%5,%6,%7}, {%8,%9}, {%0,%1,%2,%3};"
        : "+f"(d[0]), "+f"(d[1]), "+f"(d[2]), "+f"(d[3])
        : "r"(a[0]), "r"(a[1]), "r"(a[2]), "r"(a[3]), "r"(b[0]), "r"(b[1]));
}

// ---------------- zero accumulated scratch -------------------------------------
__global__ void zero_kernel() {
    int i = blockIdx.x * 256 + threadIdx.x;
    if (i < HH * MM) g_ksum[i] = 0.f;
    g_ctx[i] = 0.f;
}

// ========== projections via 3xTF32 split: dash = alpha * X @ proj^T ===========
#define PJ_PITCH 36
#define PJ_TILE  (128 * PJ_PITCH)
#define PJ_SMEM  (4 * PJ_TILE * 4)     // Ah, Al, Bh, Bl

__global__ __launch_bounds__(256) void proj_mma(
    const float* __restrict__ X, const float* __restrict__ P, float* __restrict__ C)
{
    extern __shared__ float sm[];
    float* Ah = sm;
    float* Al = sm + PJ_TILE;
    float* Bh = sm + 2 * PJ_TILE;
    float* Bl = sm + 3 * PJ_TILE;

    const int t    = threadIdx.x;
    const int lane = t & 31;
    const int w    = t >> 5;
    const int wm   = w & 3;
    const int wn   = w >> 2;
    const int grp  = lane >> 2;
    const int tig  = lane & 3;

    const long i0 = (long)blockIdx.x * 128;
    const int  j0 = blockIdx.y * 128;

    const int lrow = t >> 3;
    const int lcol = (t & 7) * 4;

    float acc[2][8][4];
#pragma unroll
    for (int mi = 0; mi < 2; ++mi)
#pragma unroll
        for (int ni = 0; ni < 8; ++ni)
#pragma unroll
            for (int r = 0; r < 4; ++r) acc[mi][ni][r] = 0.f;

#pragma unroll
    for (int c = 0; c < 2; ++c) {
        const int kof = c * 32;
#pragma unroll
        for (int i = 0; i < 4; ++i) {
            int row = i * 32 + lrow;
            float4 va = *(const float4*)(X + (i0 + row) * DD + kof + lcol);
            float4 vb = *(const float4*)(P + (long)(j0 + row) * DD + kof + lcol);
            float4 ah, al, bh, bl;
            ah.x = to_tf32(va.x); al.x = to_tf32(va.x - ah.x);
            ah.y = to_tf32(va.y); al.y = to_tf32(va.y - ah.y);
            ah.z = to_tf32(va.z); al.z = to_tf32(va.z - ah.z);
            ah.w = to_tf32(va.w); al.w = to_tf32(va.w - ah.w);
            bh.x = to_tf32(vb.x); bl.x = to_tf32(vb.x - bh.x);
            bh.y = to_tf32(vb.y); bl.y = to_tf32(vb.y - bh.y);
            bh.z = to_tf32(vb.z); bl.z = to_tf32(vb.z - bh.z);
            bh.w = to_tf32(vb.w); bl.w = to_tf32(vb.w - bh.w);
            *(float4*)&Ah[row * PJ_PITCH + lcol] = ah;
            *(float4*)&Al[row * PJ_PITCH + lcol] = al;
            *(float4*)&Bh[row * PJ_PITCH + lcol] = bh;
            *(float4*)&Bl[row * PJ_PITCH + lcol] = bl;
        }
        __syncthreads();

#pragma unroll
        for (int ks = 0; ks < 4; ++ks) {
            const int k0 = ks * 8;
            uint32_t ahr[2][4], alr[2][4];
#pragma unroll
            for (int mi = 0; mi < 2; ++mi) {
                int m = wm * 32 + mi * 16 + grp;
                ahr[mi][0] = __float_as_uint(Ah[m * PJ_PITCH + k0 + tig]);
                ahr[mi][1] = __float_as_uint(Ah[(m + 8) * PJ_PITCH + k0 + tig]);
                ahr[mi][2] = __float_as_uint(Ah[m * PJ_PITCH + k0 + tig + 4]);
                ahr[mi][3] = __float_as_uint(Ah[(m + 8) * PJ_PITCH + k0 + tig + 4]);
                alr[mi][0] = __float_as_uint(Al[m * PJ_PITCH + k0 + tig]);
                alr[mi][1] = __float_as_uint(Al[(m + 8) * PJ_PITCH + k0 + tig]);
                alr[mi][2] = __float_as_uint(Al[m * PJ_PITCH + k0 + tig + 4]);
                alr[mi][3] = __float_as_uint(Al[(m + 8) * PJ_PITCH + k0 + tig + 4]);
            }
#pragma unroll
            for (int ni = 0; ni < 8; ++ni) {
                int n = wn * 64 + ni * 8 + grp;
                uint32_t bhr[2], blr[2];
                bhr[0] = __float_as_uint(Bh[n * PJ_PITCH + k0 + tig]);
                bhr[1] = __float_as_uint(Bh[n * PJ_PITCH + k0 + tig + 4]);
                blr[0] = __float_as_uint(Bl[n * PJ_PITCH + k0 + tig]);
                blr[1] = __float_as_uint(Bl[n * PJ_PITCH + k0 + tig + 4]);
#pragma unroll
                for (int mi = 0; mi < 2; ++mi) {
                    mma_tf32_16x8x8(acc[mi][ni], ahr[mi], blr);
                    mma_tf32_16x8x8(acc[mi][ni], alr[mi], bhr);
                    mma_tf32_16x8x8(acc[mi][ni], ahr[mi], bhr);
                }
            }
        }
        __syncthreads();
    }

#pragma unroll
    for (int mi = 0; mi < 2; ++mi) {
        long row = i0 + wm * 32 + mi * 16 + grp;
#pragma unroll
        for (int ni = 0; ni < 8; ++ni) {
            long col = j0 + wn * 64 + ni * 8 + tig * 2;
            *(float2*)(C + row * MM + col) =
                make_float2(acc[mi][ni][0] * NORMALIZER, acc[mi][ni][1] * NORMALIZER);
            *(float2*)(C + (row + 8) * MM + col) =
                make_float2(acc[mi][ni][2] * NORMALIZER, acc[mi][ni][3] * NORMALIZER);
        }
    }
}

// ============ weights[h] = qp[h] @ kp[h]^T via mma.sync fp16 ===================
// Features scaled by 2^11 (no fp16 subnormals); epilogue multiplies by 2^-22.
#define WF_PITCH 40
#define WF_ABUF  (256 * WF_PITCH)       // halves per A stage
#define WF_BBUF  (128 * WF_PITCH)       // halves per B stage
#define WF_SMEM  ((2 * WF_ABUF + 2 * WF_BBUF) * 2)   // 61440 B

__global__ __launch_bounds__(256) void weights_mma(
    const __half* __restrict__ qp, const __half* __restrict__ kp, float* __restrict__ outw)
{
    extern __shared__ __half smh[];
    __half* As = smh;                   // [2][256][40]
    __half* Bs = smh + 2 * WF_ABUF;     // [2][128][40]

    const int t    = threadIdx.x;
    const int lane = t & 31;
    const int w    = t >> 5;
    const int wm   = w & 3;             // 4 warps in M (64 rows each)
    const int wn   = w >> 2;            // 2 warps in N (64 cols each)
    const int grp  = lane >> 2;
    const int tig  = lane & 3;

    const int h   = blockIdx.z;
    const long i0 = (long)blockIdx.y * 256;
    const long j0 = (long)blockIdx.x * 128;

    const __half* Ag = qp + ((long)h * NN + i0) * MM;
    const __half* Bg = kp + ((long)h * NN + j0) * MM;

    const int arow = t >> 2;            // 0..63
    const int ac8  = (t & 3) * 8;       // halves offset (8 halves = 16B)

    float acc[4][8][4];
#pragma unroll
    for (int mi = 0; mi < 4; ++mi)
#pragma unroll
        for (int ni = 0; ni < 8; ++ni)
#pragma unroll
            for (int r = 0; r < 4; ++r) acc[mi][ni][r] = 0.f;

    uint32_t As_u = smem_u32(As);
    uint32_t Bs_u = smem_u32(Bs);

    // prologue: chunk 0 -> buffer 0
#pragma unroll
    for (int i = 0; i < 4; ++i) {
        int row = i * 64 + arow;
        cp_async16(As_u + (row * WF_PITCH + ac8) * 2, Ag + (long)row * MM + ac8);
    }
#pragma unroll
    for (int i = 0; i < 2; ++i) {
        int row = i * 64 + arow;
        cp_async16(Bs_u + (row * WF_PITCH + ac8) * 2, Bg + (long)row * MM + ac8);
    }
    cp_commit();

#pragma unroll 1
    for (int c = 0; c < 8; ++c) {
        cp_wait<0>();
        __syncthreads();
        if (c < 7) {
            const int kof = (c + 1) * 32;
            const uint32_t ab = ((c + 1) & 1) * WF_ABUF * 2;
            const uint32_t bb = ((c + 1) & 1) * WF_BBUF * 2;
#pragma unroll
            for (int i = 0; i < 4; ++i) {
                int row = i * 64 + arow;
                cp_async16(As_u + ab + (row * WF_PITCH + ac8) * 2,
                           Ag + (long)row * MM + kof + ac8);
            }
#pragma unroll
            for (int i = 0; i < 2; ++i) {
                int row = i * 64 + arow;
                cp_async16(Bs_u + bb + (row * WF_PITCH + ac8) * 2,
                           Bg + (long)row * MM + kof + ac8);
            }
            cp_commit();
        }

        const __half* Ab = As + (c & 1) * WF_ABUF;
        const __half* Bb = Bs + (c & 1) * WF_BBUF;

#pragma unroll
        for (int ks = 0; ks < 2; ++ks) {
            const int k0 = ks * 16;
            uint32_t a[4][4];
#pragma unroll
            for (int mi = 0; mi < 4; ++mi) {
                int m = wm * 64 + mi * 16 + grp;
                a[mi][0] = *(const uint32_t*)&Ab[m * WF_PITCH + k0 + 2 * tig];
                a[mi][1] = *(const uint32_t*)&Ab[(m + 8) * WF_PITCH + k0 + 2 * tig];
                a[mi][2] = *(const uint32_t*)&Ab[m * WF_PITCH + k0 + 2 * tig + 8];
                a[mi][3] = *(const uint32_t*)&Ab[(m + 8) * WF_PITCH + k0 + 2 * tig + 8];
            }
            uint32_t b[8][2];
#pragma unroll
            for (int ni = 0; ni < 8; ++ni) {
                int n = wn * 64 + ni * 8 + grp;
                b[ni][0] = *(const uint32_t*)&Bb[n * WF_PITCH + k0 + 2 * tig];
                b[ni][1] = *(const uint32_t*)&Bb[n * WF_PITCH + k0 + 2 * tig + 8];
            }
#pragma unroll
            for (int mi = 0; mi < 4; ++mi)
#pragma unroll
                for (int ni = 0; ni < 8; ++ni)
                    mma_f16_16x8x16(acc[mi][ni], a[mi], b[ni]);
        }
    }

    float* Cp = outw + (long)h * NN * NN;
#pragma unroll
    for (int mi = 0; mi < 4; ++mi) {
        long row = i0 + wm * 64 + mi * 16 + grp;
#pragma unroll
        for (int ni = 0; ni < 8; ++ni) {
            long col = j0 + wn * 64 + ni * 8 + tig * 2;
            *(float2*)(Cp + row * NN + col) =
                make_float2(acc[mi][ni][0] * HUNSCALE, acc[mi][ni][1] * HUNSCALE);
            *(float2*)(Cp + (row + 8) * NN + col) =
                make_float2(acc[mi][ni][2] * HUNSCALE, acc[mi][ni][3] * HUNSCALE);
        }
    }
}

// ======= ctx[h][m][e] = sum_n kp[h][n][m] * v[h][n][e]  via mma tf32 ==========
#define CTX_KSPLIT 16
#define CTX_KC     32
#define KS_PITCH   260
#define VS_PITCH   68
#define KS_BUF     (CTX_KC * KS_PITCH)
#define VS_BUF     (CTX_KC * VS_PITCH)
#define CTX_SMEM   ((2 * KS_BUF + 2 * VS_BUF) * 4)

__global__ __launch_bounds__(256) void ctx_mma(
    const float* __restrict__ kp, const float* __restrict__ v, float* __restrict__ ctx)
{
    extern __shared__ float sm[];
    float* Ks = sm;                    // [2][32][260]
    float* Vs = sm + 2 * KS_BUF;       // [2][32][68]

    const int t    = threadIdx.x;
    const int lane = t & 31;
    const int w    = t >> 5;
    const int wm   = w & 3;
    const int we   = w >> 2;
    const int grp  = lane >> 2;
    const int tig  = lane & 3;

    const int h     = blockIdx.z;
    const int nbase = blockIdx.y * (NN / CTX_KSPLIT);

    const float* Kg = kp + ((long)h * NN + nbase) * MM;
    const float* Vg = v  + ((long)h * NN + nbase) * DD;

    const int krow = t >> 3;
    const int c4   = t & 7;

    float acc[4][4][4];
#pragma unroll
    for (int mi = 0; mi < 4; ++mi)
#pragma unroll
        for (int ni = 0; ni < 4; ++ni)
#pragma unroll
            for (int r = 0; r < 4; ++r) acc[mi][ni][r] = 0.f;

    uint32_t Ks_u = smem_u32(Ks);
    uint32_t Vs_u = smem_u32(Vs);

#pragma unroll
    for (int i = 0; i < 8; ++i)
        cp_async16(Ks_u + (krow * KS_PITCH + (c4 + i * 8) * 4) * 4,
                   Kg + (long)krow * MM + (c4 + i * 8) * 4);
#pragma unroll
    for (int i = 0; i < 2; ++i)
        cp_async16(Vs_u + (krow * VS_PITCH + (c4 + i * 8) * 4) * 4,
                   Vg + (long)krow * DD + (c4 + i * 8) * 4);
    cp_commit();

#pragma unroll 1
    for (int c = 0; c < 8; ++c) {
        cp_wait<0>();
        __syncthreads();
        if (c < 7) {
            const int nof = (c + 1) * CTX_KC;
            const uint32_t kb = ((c + 1) & 1) * KS_BUF * 4;
            const uint32_t vb = ((c + 1) & 1) * VS_BUF * 4;
#pragma unroll
            for (int i = 0; i < 8; ++i)
                cp_async16(Ks_u + kb + (krow * KS_PITCH + (c4 + i * 8) * 4) * 4,
                           Kg + (long)(nof + krow) * MM + (c4 + i * 8) * 4);
#pragma unroll
            for (int i = 0; i < 2; ++i)
                cp_async16(Vs_u + vb + (krow * VS_PITCH + (c4 + i * 8) * 4) * 4,
                           Vg + (long)(nof + krow) * DD + (c4 + i * 8) * 4);
            cp_commit();
        }

        const float* Kb = Ks + (c & 1) * KS_BUF;
        const float* Vb = Vs + (c & 1) * VS_BUF;

#pragma unroll
        for (int ks = 0; ks < 4; ++ks) {
            const int k0 = ks * 8;
            uint32_t a[4][4];
#pragma unroll
            for (int mi = 0; mi < 4; ++mi) {
                int m = wm * 64 + mi * 16 + grp;
                a[mi][0] = __float_as_uint(Kb[(k0 + tig) * KS_PITCH + m]);
                a[mi][1] = __float_as_uint(Kb[(k0 + tig) * KS_PITCH + m + 8]);
                a[mi][2] = __float_as_uint(Kb[(k0 + tig + 4) * KS_PITCH + m]);
                a[mi][3] = __float_as_uint(Kb[(k0 + tig + 4) * KS_PITCH + m + 8]);
            }
            uint32_t b[4][2];
#pragma unroll
            for (int ni = 0; ni < 4; ++ni) {
                int e = we * 32 + ni * 8 + grp;
                b[ni][0] = to_tf32_u(Vb[(k0 + tig) * VS_PITCH + e]);
                b[ni][1] = to_tf32_u(Vb[(k0 + tig + 4) * VS_PITCH + e]);
            }
#pragma unroll
            for (int mi = 0; mi < 4; ++mi)
#pragma unroll
                for (int ni = 0; ni < 4; ++ni)
                    mma_tf32_16x8x8(acc[mi][ni], a[mi], b[ni]);
        }
    }

#pragma unroll
    for (int mi = 0; mi < 4; ++mi) {
        int m = wm * 64 + mi * 16 + grp;
#pragma unroll
        for (int ni = 0; ni < 4; ++ni) {
            int e = we * 32 + ni * 8 + tig * 2;
            float* p0 = &ctx[((long)h * MM + m) * DD + e];
            float* p1 = &ctx[((long)h * MM + m + 8) * DD + e];
            atomicAdd(p0,     acc[mi][ni][0]);
            atomicAdd(p0 + 1, acc[mi][ni][1]);
            atomicAdd(p1,     acc[mi][ni][2]);
            atomicAdd(p1 + 1, acc[mi][ni][3]);
        }
    }
}

// ======= out[h][n][e] = dinv[n] * sum_m qp[h][n][m] * ctx[h][m][e]  (mma) =====
#define OQ_PITCH 36
#define OC_PITCH 68
#define OQ_BUF   (128 * OQ_PITCH)
#define OC_BUF   (32 * OC_PITCH)
#define OUT_SMEM ((2 * OQ_BUF + 2 * OC_BUF) * 4)

__global__ __launch_bounds__(256) void out_mma(
    const float* __restrict__ qp, const float* __restrict__ ctx,
    const float* __restrict__ dinv, float* __restrict__ out)
{
    extern __shared__ float sm[];
    float* Qs = sm;                    // [2][128][36]
    float* Cs = sm + 2 * OQ_BUF;       // [2][32][68]

    const int t    = threadIdx.x;
    const int lane = t & 31;
    const int w    = t >> 5;
    const int wn   = w & 3;
    const int we   = w >> 2;
    const int grp  = lane >> 2;
    const int tig  = lane & 3;

    const int h  = blockIdx.y;
    const long n0 = (long)blockIdx.x * 128;

    const float* Qg = qp  + ((long)h * NN + n0) * MM;
    const float* Cg = ctx + (long)h * MM * DD;

    const int lrow = t >> 3;
    const int lcol = (t & 7) * 4;
    const int crow = t >> 3;
    const int cc4  = t & 7;

    float acc[2][4][4];
#pragma unroll
    for (int mi = 0; mi < 2; ++mi)
#pragma unroll
        for (int ni = 0; ni < 4; ++ni)
#pragma unroll
            for (int r = 0; r < 4; ++r) acc[mi][ni][r] = 0.f;

    uint32_t Qs_u = smem_u32(Qs);
    uint32_t Cs_u = smem_u32(Cs);

#pragma unroll
    for (int i = 0; i < 4; ++i) {
        int row = i * 32 + lrow;
        cp_async16(Qs_u + (row * OQ_PITCH + lcol) * 4, Qg + (long)row * MM + lcol);
    }
#pragma unroll
    for (int i = 0; i < 2; ++i)
        cp_async16(Cs_u + (crow * OC_PITCH + (cc4 + i * 8) * 4) * 4,
                   Cg + (long)crow * DD + (cc4 + i * 8) * 4);
    cp_commit();

#pragma unroll 1
    for (int c = 0; c < 8; ++c) {
        cp_wait<0>();
        __syncthreads();
        if (c < 7) {
            const int kof = (c + 1) * 32;
            const uint32_t qb = ((c + 1) & 1) * OQ_BUF * 4;
            const uint32_t cb = ((c + 1) & 1) * OC_BUF * 4;
#pragma unroll
            for (int i = 0; i < 4; ++i) {
                int row = i * 32 + lrow;
                cp_async16(Qs_u + qb + (row * OQ_PITCH + lcol) * 4,
                           Qg + (long)row * MM + kof + lcol);
            }
#pragma unroll
            for (int i = 0; i < 2; ++i)
                cp_async16(Cs_u + cb + (crow * OC_PITCH + (cc4 + i * 8) * 4) * 4,
                           Cg + (long)(kof + crow) * DD + (cc4 + i * 8) * 4);
            cp_commit();
        }

        const float* Qb = Qs + (c & 1) * OQ_BUF;
        const float* Cb = Cs + (c & 1) * OC_BUF;

#pragma unroll
        for (int ks = 0; ks < 4; ++ks) {
            const int k0 = ks * 8;
            uint32_t a[2][4];
#pragma unroll
            for (int mi = 0; mi < 2; ++mi) {
                int n = wn * 32 + mi * 16 + grp;
                a[mi][0] = __float_as_uint(Qb[n * OQ_PITCH + k0 + tig]);
                a[mi][1] = __float_as_uint(Qb[(n + 8) * OQ_PITCH + k0 + tig]);
                a[mi][2] = __float_as_uint(Qb[n * OQ_PITCH + k0 + tig + 4]);
                a[mi][3] = __float_as_uint(Qb[(n + 8) * OQ_PITCH + k0 + tig + 4]);
            }
            uint32_t b[4][2];
#pragma unroll
            for (int ni = 0; ni < 4; ++ni) {
                int e = we * 32 + ni * 8 + grp;
                b[ni][0] = to_tf32_u(Cb[(k0 + tig) * OC_PITCH + e]);
                b[ni][1] = to_tf32_u(Cb[(k0 + tig + 4) * OC_PITCH + e]);
            }
#pragma unroll
            for (int mi = 0; mi < 2; ++mi)
#pragma unroll
                for (int ni = 0; ni < 4; ++ni)
                    mma_tf32_16x8x8(acc[mi][ni], a[mi], b[ni]);
        }
    }

#pragma unroll
    for (int mi = 0; mi < 2; ++mi) {
        long n = n0 + wn * 32 + mi * 16 + grp;
        float dv0 = dinv[(long)h * NN + n];
        float dv1 = dinv[(long)h * NN + n + 8];
#pragma unroll
        for (int ni = 0; ni < 4; ++ni) {
            int e = we * 32 + ni * 8 + tig * 2;
            *(float2*)(out + ((long)h * NN + n) * DD + e) =
                make_float2(acc[mi][ni][0] * dv0, acc[mi][ni][1] * dv0);
            *(float2*)(out + ((long)h * NN + n + 8) * DD + e) =
                make_float2(acc[mi][ni][2] * dv1, acc[mi][ni][3] * dv1);
        }
    }
}

// ---------------- diag / kmax / exp / dinv -------------------------------------
__global__ void diag_kernel(const float* __restrict__ x, float* __restrict__ out) {
    int row  = blockIdx.x * 8 + (threadIdx.x >> 5);
    int lane = threadIdx.x & 31;
    const float* p = x + (long)row * DD;
    float a = p[lane], b = p[lane + 32];
    float s = a * a + b * b;
#pragma unroll
    for (int o = 16; o; o >>= 1) s += __shfl_xor_sync(0xffffffffu, s, o);
    if (!lane) out[row] = s * DIAG_COEF;
}

__global__ void kmax1_kernel(const float* __restrict__ d, float* __restrict__ part, int n) {
    float m = -3.4e38f;
    for (int i = blockIdx.x * blockDim.x + threadIdx.x; i < n; i += gridDim.x * blockDim.x)
        m = fmaxf(m, d[i]);
    __shared__ float sm[8];
#pragma unroll
    for (int o = 16; o; o >>= 1) m = fmaxf(m, __shfl_xor_sync(0xffffffffu, m, o));
    if ((threadIdx.x & 31) == 0) sm[threadIdx.x >> 5] = m;
    __syncthreads();
    if (threadIdx.x == 0) {
        float b = sm[0];
#pragma unroll
        for (int w = 1; w < 8; ++w) b = fmaxf(b, sm[w]);
        part[blockIdx.x] = b;
    }
}

__global__ void kmax2_kernel(const float* __restrict__ part, float* __restrict__ out, int n) {
    float m = -3.4e38f;
    for (int i = threadIdx.x; i < n; i += 256) m = fmaxf(m, part[i]);
    __shared__ float sm[8];
#pragma unroll
    for (int o = 16; o; o >>= 1) m = fmaxf(m, __shfl_xor_sync(0xffffffffu, m, o));
    if ((threadIdx.x & 31) == 0) sm[threadIdx.x >> 5] = m;
    __syncthreads();
    if (threadIdx.x == 0) {
        float b = sm[0];
#pragma unroll
        for (int w = 1; w < 8; ++w) b = fmaxf(b, sm[w]);
        out[0] = b;
    }
}

// exp kernels also emit scaled-fp16 copies of the features for the weights GEMM
__global__ void expq_kernel(float* __restrict__ dash, const float* __restrict__ diag,
                            __half* __restrict__ dash_h) {
    long row = blockIdx.x;
    int  t   = threadIdx.x;
    long idx = row * MM + t;
    float x = dash[idx];
    float m = x;
#pragma unroll
    for (int o = 16; o; o >>= 1) m = fmaxf(m, __shfl_xor_sync(0xffffffffu, m, o));
    __shared__ float sm[8];
    if ((t & 31) == 0) sm[t >> 5] = m;
    __syncthreads();
    float bm = sm[0];
#pragma unroll
    for (int w = 1; w < 8; ++w) bm = fmaxf(bm, sm[w]);
    float v = RATIO * (expf(x - diag[row] - bm) + FEPS);
    dash[idx]   = to_tf32(v);
    dash_h[idx] = __float2half_rn(v * HSCALE);
}

__global__ void expk_kernel(float* __restrict__ dash, const float* __restrict__ diag,
                            const float* __restrict__ kmax, float* __restrict__ ksum,
                            __half* __restrict__ dash_h) {
    int t    = threadIdx.x;
    int row0 = blockIdx.x * 64;
    int h    = row0 >> 12;
    float stab  = kmax[0];
    float local = 0.f;
    for (int r = 0; r < 64; ++r) {
        long idx = (long)(row0 + r) * MM + t;
        float vfull = RATIO * (expf(dash[idx] - diag[row0 + r] - stab) + FEPS);
        float vv = to_tf32(vfull);
        dash[idx]   = vv;
        dash_h[idx] = __float2half_rn(vfull * HSCALE);
        local += vv;
    }
    atomicAdd(&ksum[h * MM + t], local);
}

__global__ void dinv_kernel(const float* __restrict__ qp, const float* __restrict__ ksum,
                            float* __restrict__ dinv) {
    int row  = blockIdx.x * 8 + (threadIdx.x >> 5);
    int lane = threadIdx.x & 31;
    int h    = row >> 12;
    const float* qr = qp + (long)row * MM;
    const float* ks = ksum + h * MM;
    float s = 0.f;
#pragma unroll
    for (int i = 0; i < 8; ++i) {
        int m = lane + i * 32;
        s += qr[m] * ks[m];
    }
#pragma unroll
    for (int o = 16; o; o >>= 1) s += __shfl_xor_sync(0xffffffffu, s, o);
    if (!lane) dinv[row] = 1.f / s;
}

// -------------------------------------------------------------------------------
extern "C" void kernel_launch(void* const* d_in, const int* in_sizes, int n_in,
                              void* d_out, int out_size)
{
    const float* q    = (const float*)d_in[0];
    const float* k    = (const float*)d_in[1];
    const float* v    = (const float*)d_in[2];
    const float* proj = (const float*)d_in[3];

    float* out_align = (float*)d_out;                       // [H,N,D]
    float* out_w     = out_align + (long)HH * NN * DD;      // [H,N,N]

    float *qp, *kp, *qdiag, *kdiag, *ksum, *dinv, *ctx, *kpart, *kmax;
    __half *qph, *kph;
    cudaGetSymbolAddress((void**)&qp,    g_qp);
    cudaGetSymbolAddress((void**)&kp,    g_kp);
    cudaGetSymbolAddress((void**)&qph,   g_qph);
    cudaGetSymbolAddress((void**)&kph,   g_kph);
    cudaGetSymbolAddress((void**)&qdiag, g_qdiag);
    cudaGetSymbolAddress((void**)&kdiag, g_kdiag);
    cudaGetSymbolAddress((void**)&ksum,  g_ksum);
    cudaGetSymbolAddress((void**)&dinv,  g_dinv);
    cudaGetSymbolAddress((void**)&ctx,   g_ctx);
    cudaGetSymbolAddress((void**)&kpart, g_kpart);
    cudaGetSymbolAddress((void**)&kmax,  g_kmax);

    static bool attr_done = false;
    if (!attr_done) {
        cudaFuncSetAttribute(weights_mma, cudaFuncAttributeMaxDynamicSharedMemorySize, WF_SMEM);
        cudaFuncSetAttribute(proj_mma,    cudaFuncAttributeMaxDynamicSharedMemorySize, PJ_SMEM);
        cudaFuncSetAttribute(ctx_mma,     cudaFuncAttributeMaxDynamicSharedMemorySize, CTX_SMEM);
        cudaFuncSetAttribute(out_mma,     cudaFuncAttributeMaxDynamicSharedMemorySize, OUT_SMEM);
        attr_done = true;
    }

    zero_kernel<<<HH * MM * DD / 256, 256>>>();

    proj_mma<<<dim3(ROWS / 128, MM / 128), 256, PJ_SMEM>>>(q, proj, qp);
    proj_mma<<<dim3(ROWS / 128, MM / 128), 256, PJ_SMEM>>>(k, proj, kp);

    diag_kernel<<<ROWS / 8, 256>>>(q, qdiag);
    diag_kernel<<<ROWS / 8, 256>>>(k, kdiag);

    kmax1_kernel<<<1024, 256>>>(kp, kpart, ROWS * MM);
    kmax2_kernel<<<1, 256>>>(kpart, kmax, 1024);

    expq_kernel<<<ROWS, 256>>>(qp, qdiag, qph);
    expk_kernel<<<ROWS / 64, 256>>>(kp, kdiag, kmax, ksum, kph);

    // dominant GEMM: fp16 m16n8k16, scaled to avoid fp16 subnormals
    weights_mma<<<dim3(NN / 128, NN / 256, HH), 256, WF_SMEM>>>(qph, kph, out_w);

    ctx_mma<<<dim3(1, CTX_KSPLIT, HH), 256, CTX_SMEM>>>(kp, v, ctx);
    dinv_kernel<<<ROWS / 8, 256>>>(qp, ksum, dinv);
    out_mma<<<dim3(NN / 128, HH), 256, OUT_SMEM>>>(qp, ctx, dinv, out_align);
}